// round 1
// baseline (speedup 1.0000x reference)
#include <cuda_runtime.h>

#define BATCH 8
#define CIN   512
#define HW    1024
#define NHEAD 8
#define QKV_CH 768

// Scratch (device globals; no allocation allowed)
__device__ float g_qkv[BATCH * QKV_CH * HW];   // [b][768][1024]
__device__ float g_af [BATCH * 256   * HW];    // attention output, already in the
                                               // reference's scrambled reshape layout

// ---------------------------------------------------------------------------
// Generic batched GEMM: Y[b][m][n] = sum_k W[m][k] * X[b][k][n] + bias[m]
// Rows m < SCALE_ROWS additionally scaled by scaleVal AFTER bias (q-scaling).
// 128x128 tile, BK=16, 256 threads, 8x8 per thread.
// ---------------------------------------------------------------------------
template<int M, int K, int N, int SCALE_ROWS>
__global__ __launch_bounds__(256, 2)
void gemm_bias(const float* __restrict__ W, const float* __restrict__ X,
               const float* __restrict__ bias, float* __restrict__ Y,
               float scaleVal)
{
    __shared__ float Ws[16][132];   // [k][m], padded
    __shared__ float Xs[16][128];   // [k][n]

    const int b  = blockIdx.z;
    const int m0 = blockIdx.y * 128;
    const int n0 = blockIdx.x * 128;
    const float* Xb = X + (size_t)b * K * N;
    float*       Yb = Y + (size_t)b * M * N;

    const int t  = threadIdx.x;
    const int tx = t & 15;          // n direction
    const int ty = t >> 4;          // m direction

    const int wrow  = t >> 1;       // 0..127
    const int whalf = t & 1;        // which 8-wide k half
    const int xrow  = t >> 4;       // 0..15
    const int xcol  = t & 15;       // float4 col

    float acc[8][8];
#pragma unroll
    for (int i = 0; i < 8; i++)
#pragma unroll
        for (int j = 0; j < 8; j++) acc[i][j] = 0.f;

    for (int k0 = 0; k0 < K; k0 += 16) {
        // ---- load W tile [128 x 16] -> Ws[k][m] (transpose) ----
        float4 w0 = *(const float4*)&W[(size_t)(m0 + wrow) * K + k0 + whalf * 8];
        float4 w1 = *(const float4*)&W[(size_t)(m0 + wrow) * K + k0 + whalf * 8 + 4];
        Ws[whalf * 8 + 0][wrow] = w0.x;
        Ws[whalf * 8 + 1][wrow] = w0.y;
        Ws[whalf * 8 + 2][wrow] = w0.z;
        Ws[whalf * 8 + 3][wrow] = w0.w;
        Ws[whalf * 8 + 4][wrow] = w1.x;
        Ws[whalf * 8 + 5][wrow] = w1.y;
        Ws[whalf * 8 + 6][wrow] = w1.z;
        Ws[whalf * 8 + 7][wrow] = w1.w;
        // ---- load X tile [16 x 128] ----
        *(float4*)&Xs[xrow][xcol * 4] =
            *(const float4*)&Xb[(size_t)(k0 + xrow) * N + n0 + xcol * 4];
        *(float4*)&Xs[xrow][xcol * 4 + 64] =
            *(const float4*)&Xb[(size_t)(k0 + xrow) * N + n0 + xcol * 4 + 64];
        __syncthreads();

#pragma unroll
        for (int kk = 0; kk < 16; kk++) {
            float a[8], bb[8];
            *(float4*)&a[0]  = *(float4*)&Ws[kk][ty * 8];
            *(float4*)&a[4]  = *(float4*)&Ws[kk][ty * 8 + 4];
            *(float4*)&bb[0] = *(float4*)&Xs[kk][tx * 8];
            *(float4*)&bb[4] = *(float4*)&Xs[kk][tx * 8 + 4];
#pragma unroll
            for (int i = 0; i < 8; i++)
#pragma unroll
                for (int j = 0; j < 8; j++)
                    acc[i][j] += a[i] * bb[j];
        }
        __syncthreads();
    }

    // ---- epilogue: bias, optional row scale, store ----
#pragma unroll
    for (int i = 0; i < 8; i++) {
        int m = m0 + ty * 8 + i;
        float bv = bias[m];
        float sc = (m < SCALE_ROWS) ? scaleVal : 1.f;
        float4 o0, o1;
        o0.x = (acc[i][0] + bv) * sc;
        o0.y = (acc[i][1] + bv) * sc;
        o0.z = (acc[i][2] + bv) * sc;
        o0.w = (acc[i][3] + bv) * sc;
        o1.x = (acc[i][4] + bv) * sc;
        o1.y = (acc[i][5] + bv) * sc;
        o1.z = (acc[i][6] + bv) * sc;
        o1.w = (acc[i][7] + bv) * sc;
        *(float4*)&Yb[(size_t)m * N + n0 + tx * 8]     = o0;
        *(float4*)&Yb[(size_t)m * N + n0 + tx * 8 + 4] = o1;
    }
}

// ---------------------------------------------------------------------------
// Fused attention: logits (d=32 inner) -> softmax across the 8 HEADS (axis=1
// of the reference!) -> weights @ V, for one (b, 32-wide q-tile) per block.
// Thread t = (head n = t>>5, q-lane qi = t&31). k processed in tiles of 16.
// Output written directly in the reference's flat-reshape (scrambled) layout:
//   AF[b][n*32 + (q>>5)][(q&31)*32 + d] = A[b][n][q][d]
// ---------------------------------------------------------------------------
__global__ __launch_bounds__(256, 2)
void attn_fused(const float* __restrict__ qkv, float* __restrict__ af)
{
    extern __shared__ float sm[];
    float* Qs = sm;                       // [8][32][32]  (n, d, qi)   8192 f
    float* Ks = Qs + 8 * 32 * 32;         // [8][32][16]  (n, d, ki)   4096 f
    float* Vs = Ks + 8 * 32 * 16;         // [8][16][36]  (n, ki, d+pad) 4608 f
    float* Es = Vs + 8 * 16 * 36;         // [8][16][32]  (n, ki, qi)  4096 f

    const int b  = blockIdx.y;
    const int q0 = blockIdx.x * 32;
    const int t  = threadIdx.x;
    const int n  = t >> 5;
    const int qi = t & 31;

    const float* qb = qkv + (size_t)b * QKV_CH * HW;

    // load Q tile for all heads: Qs[n][d][qi]
    for (int i = t; i < 8192; i += 256) {
        int nn = i >> 10, dd = (i >> 5) & 31, qq = i & 31;
        Qs[i] = qb[(size_t)(nn * 32 + dd) * HW + q0 + qq];
    }

    float acc[32];
#pragma unroll
    for (int d = 0; d < 32; d++) acc[d] = 0.f;

    const float*  qcol = Qs + n * 1024 + qi;           // stride 32 over d
    const float4* krow = (const float4*)(Ks + n * 512);

    for (int kt = 0; kt < 64; kt++) {
        const int k0 = kt * 16;
        __syncthreads();   // protect Ks/Vs/Es reuse (also covers Qs on iter 0)

        // K tile: Ks[n][d][ki]  (gmem-coalesced over ki)
        for (int i = t; i < 4096; i += 256) {
            int nn = i >> 9, dd = (i >> 4) & 31, ki = i & 15;
            Ks[i] = qb[(size_t)(256 + nn * 32 + dd) * HW + k0 + ki];
        }
        // V tile: read (n,d,ki) coalesced, store transposed Vs[n][ki][d]
        for (int i = t; i < 4096; i += 256) {
            int nn = i >> 9, dd = (i >> 4) & 31, ki = i & 15;
            Vs[(nn * 16 + ki) * 36 + dd] =
                qb[(size_t)(512 + nn * 32 + dd) * HW + k0 + ki];
        }
        __syncthreads();

        // logits for this head: l[ki] = sum_d Q[n][d][q] * K[n][d][k]
        float l[16];
#pragma unroll
        for (int ki = 0; ki < 16; ki++) l[ki] = 0.f;
#pragma unroll
        for (int d = 0; d < 32; d++) {
            float qv = qcol[d * 32];
            float4 k0v = krow[d * 4 + 0];
            float4 k1v = krow[d * 4 + 1];
            float4 k2v = krow[d * 4 + 2];
            float4 k3v = krow[d * 4 + 3];
            l[0]  += qv * k0v.x;  l[1]  += qv * k0v.y;
            l[2]  += qv * k0v.z;  l[3]  += qv * k0v.w;
            l[4]  += qv * k1v.x;  l[5]  += qv * k1v.y;
            l[6]  += qv * k1v.z;  l[7]  += qv * k1v.w;
            l[8]  += qv * k2v.x;  l[9]  += qv * k2v.y;
            l[10] += qv * k2v.z;  l[11] += qv * k2v.w;
            l[12] += qv * k3v.x;  l[13] += qv * k3v.y;
            l[14] += qv * k3v.z;  l[15] += qv * k3v.w;
        }
        // exp (logits are O(1); no max-shift needed, matches softmax exactly)
#pragma unroll
        for (int ki = 0; ki < 16; ki++) {
            l[ki] = __expf(l[ki]);
            Es[(n * 16 + ki) * 32 + qi] = l[ki];   // lane-stride-1 store
        }
        __syncthreads();

        // softmax across heads + accumulate weights @ V
#pragma unroll
        for (int ki = 0; ki < 16; ki++) {
            float denom = 0.f;
#pragma unroll
            for (int nn = 0; nn < 8; nn++)
                denom += Es[(nn * 16 + ki) * 32 + qi];
            float w = __fdividef(l[ki], denom);
            const float4* vp = (const float4*)(Vs + (n * 16 + ki) * 36);
#pragma unroll
            for (int d4 = 0; d4 < 8; d4++) {
                float4 v = vp[d4];
                acc[d4 * 4 + 0] += w * v.x;
                acc[d4 * 4 + 1] += w * v.y;
                acc[d4 * 4 + 2] += w * v.z;
                acc[d4 * 4 + 3] += w * v.w;
            }
        }
    }

    // write in scrambled (flat-reshape) layout for the output projection GEMM
    const int q  = q0 + qi;
    const int cc = n * 32 + (q >> 5);
    const int sb = (q & 31) * 32;
    float* out = af + ((size_t)b * 256 + cc) * HW + sb;
#pragma unroll
    for (int d4 = 0; d4 < 8; d4++) {
        float4 o;
        o.x = acc[d4 * 4 + 0];
        o.y = acc[d4 * 4 + 1];
        o.z = acc[d4 * 4 + 2];
        o.w = acc[d4 * 4 + 3];
        *(float4*)&out[d4 * 4] = o;
    }
}

// ---------------------------------------------------------------------------
extern "C" void kernel_launch(void* const* d_in, const int* in_sizes, int n_in,
                              void* d_out, int out_size)
{
    const float* x      = (const float*)d_in[0];   // [8,512,32,32]
    const float* w_qkv  = (const float*)d_in[1];   // [768,512]
    const float* b_qkv  = (const float*)d_in[2];   // [768]
    const float* w_attn = (const float*)d_in[3];   // [512,256]
    const float* b_attn = (const float*)d_in[4];   // [512]
    float* out = (float*)d_out;                    // [8,512,32,32]

    void* qkvp = nullptr;
    void* afp  = nullptr;
    cudaGetSymbolAddress(&qkvp, g_qkv);
    cudaGetSymbolAddress(&afp,  g_af);

    const int attn_smem = (8192 + 4096 + 4608 + 4096) * (int)sizeof(float); // 82 KB
    cudaFuncSetAttribute(attn_fused,
                         cudaFuncAttributeMaxDynamicSharedMemorySize, attn_smem);

    // 1) QKV projection (+bias, q rows scaled by 32^-0.5)
    gemm_bias<768, 512, 1024, 256><<<dim3(8, 6, BATCH), 256>>>(
        w_qkv, x, b_qkv, (float*)qkvp, 0.17677669529663687f);

    // 2) fused logits -> head-softmax -> AV, output in scrambled layout
    attn_fused<<<dim3(32, BATCH), 256, attn_smem>>>((const float*)qkvp,
                                                    (float*)afp);

    // 3) output projection (+bias)
    gemm_bias<512, 256, 1024, 0><<<dim3(8, 4, BATCH), 256>>>(
        w_attn, (const float*)afp, b_attn, out, 1.0f);
}

// round 3
// speedup vs baseline: 1.3477x; 1.3477x over previous
#include <cuda_runtime.h>
#include <cstdint>

#define BATCH 8
#define CIN   512
#define HW    1024
#define NHEAD 8
#define QKV_CH 768

// Scratch (device globals; no allocation allowed)
__device__ float g_qkv[BATCH * QKV_CH * HW];   // [b][768][1024]
__device__ float g_af [BATCH * 256   * HW];    // attention out, scrambled reshape layout

// ===========================================================================
// helpers
// ===========================================================================
__device__ __forceinline__ uint32_t f2tf32(float v) {
    uint32_t r;
    asm("cvt.rna.tf32.f32 %0, %1;" : "=r"(r) : "f"(v));
    return r;
}
__device__ __forceinline__ void mma1688(float* c, const uint32_t* a, const uint32_t* b) {
    asm volatile("mma.sync.aligned.m16n8k8.row.col.f32.tf32.tf32.f32 "
        "{%0,%1,%2,%3}, {%4,%5,%6,%7}, {%8,%9}, {%0,%1,%2,%3};"
        : "+f"(c[0]), "+f"(c[1]), "+f"(c[2]), "+f"(c[3])
        : "r"(a[0]), "r"(a[1]), "r"(a[2]), "r"(a[3]), "r"(b[0]), "r"(b[1]));
}

// packed fp32x2 (exact fp32 math at 2x pipe rate)
typedef unsigned long long ull;
__device__ __forceinline__ void fma2(ull& d, ull a, ull b) {
    asm("fma.rn.f32x2 %0, %1, %2, %0;" : "+l"(d) : "l"(a), "l"(b));
}
__device__ __forceinline__ ull fma2v(ull a, ull b, ull c) {
    ull d; asm("fma.rn.f32x2 %0, %1, %2, %3;" : "=l"(d) : "l"(a), "l"(b), "l"(c)); return d;
}
__device__ __forceinline__ ull mul2v(ull a, ull b) {
    ull d; asm("mul.rn.f32x2 %0, %1, %2;" : "=l"(d) : "l"(a), "l"(b)); return d;
}
__device__ __forceinline__ ull add2v(ull a, ull b) {
    ull d; asm("add.rn.f32x2 %0, %1, %2;" : "=l"(d) : "l"(a), "l"(b)); return d;
}
__device__ __forceinline__ ull dup2(float v) {
    ull r; uint32_t u = __float_as_uint(v);
    asm("mov.b64 %0, {%1, %1};" : "=l"(r) : "r"(u));
    return r;
}
__device__ __forceinline__ ull pk2(float x, float y) {
    ull r; uint32_t a = __float_as_uint(x), b = __float_as_uint(y);
    asm("mov.b64 %0, {%1, %2};" : "=l"(r) : "r"(a), "r"(b));
    return r;
}
__device__ __forceinline__ void unpk2(ull v, float& x, float& y) {
    uint32_t a, b;
    asm("mov.b64 {%0, %1}, %2;" : "=r"(a), "=r"(b) : "l"(v));
    x = __uint_as_float(a); y = __uint_as_float(b);
}
// FMA-pipe reciprocal (no MUFU): bit-trick guess + 3 Newton steps, ~1e-10 rel
__device__ __forceinline__ float frcp(float x) {
    float r = __int_as_float(0x7EF311C3 - __float_as_int(x));
    r = r * (2.0f - x * r);
    r = r * (2.0f - x * r);
    r = r * (2.0f - x * r);
    return r;
}

// ===========================================================================
// tf32 mma.sync GEMM: Y[b][m][n] = sum_k W[m][k] * X[b][k][n] + bias[m]
// rows m < SCALE_ROWS additionally scaled by scaleVal (q-scaling).
// CTA tile 128x128, BK=32, 256 threads = 8 warps (2m x 4n), warp tile 64x32.
// Double-buffered smem; conflict-free strides (As [m][k]+36, Bs [k][n]+136).
// ===========================================================================
#define AS_STRIDE 36
#define BS_STRIDE 136
static constexpr int GEMM_SMEM = (2 * 128 * AS_STRIDE + 2 * 32 * BS_STRIDE) * 4; // 71680

template<int M, int K, int SCALE_ROWS>
__global__ __launch_bounds__(256, 2)
void gemm_mma(const float* __restrict__ W, const float* __restrict__ X,
              const float* __restrict__ bias, float* __restrict__ Y,
              float scaleVal)
{
    extern __shared__ char smraw[];
    uint32_t* As = (uint32_t*)smraw;                    // [2][128][36]
    uint32_t* Bs = (uint32_t*)smraw + 2 * 128 * AS_STRIDE; // [2][32][136]

    const int t    = threadIdx.x;
    const int lane = t & 31;
    const int wid  = t >> 5;
    const int g    = lane >> 2;
    const int t4   = lane & 3;
    const int wm   = (wid & 1) * 64;
    const int wn   = (wid >> 1) * 32;
    const int b    = blockIdx.z;
    const int m0   = blockIdx.y * 128;
    const int n0   = blockIdx.x * 128;
    const float* Xb = X + (size_t)b * K * 1024;
    float*       Yb = Y + (size_t)b * M * 1024;

    // staging coords
    const int am = t >> 3;         // + c*32  -> m row 0..127
    const int ak = (t & 7) * 4;    // k quad
    const int bk = t >> 5;         // + c*8   -> k row 0..31
    const int bn = (t & 31) * 4;   // n quad

    float4 aw[4], bw[4];
    float acc[4][4][4];
#pragma unroll
    for (int i = 0; i < 4; i++)
#pragma unroll
        for (int j = 0; j < 4; j++)
#pragma unroll
            for (int q = 0; q < 4; q++) acc[i][j][q] = 0.f;

    auto LOADR = [&](int kc) {
#pragma unroll
        for (int c = 0; c < 4; c++)
            aw[c] = *(const float4*)&W[(size_t)(m0 + am + c * 32) * K + kc * 32 + ak];
#pragma unroll
        for (int c = 0; c < 4; c++)
            bw[c] = *(const float4*)&Xb[(size_t)(kc * 32 + bk + c * 8) * 1024 + n0 + bn];
    };
    auto STORE = [&](int st) {
        uint32_t* A  = As + st * 128 * AS_STRIDE;
        uint32_t* Bm = Bs + st * 32 * BS_STRIDE;
#pragma unroll
        for (int c = 0; c < 4; c++) {
            uint4 v;
            v.x = f2tf32(aw[c].x); v.y = f2tf32(aw[c].y);
            v.z = f2tf32(aw[c].z); v.w = f2tf32(aw[c].w);
            *(uint4*)&A[(am + c * 32) * AS_STRIDE + ak] = v;
        }
#pragma unroll
        for (int c = 0; c < 4; c++) {
            uint4 v;
            v.x = f2tf32(bw[c].x); v.y = f2tf32(bw[c].y);
            v.z = f2tf32(bw[c].z); v.w = f2tf32(bw[c].w);
            *(uint4*)&Bm[(bk + c * 8) * BS_STRIDE + bn] = v;
        }
    };

    const int NC = K / 32;
    LOADR(0);
    STORE(0);
    __syncthreads();

    for (int kc = 0; kc < NC; kc++) {
        if (kc + 1 < NC) LOADR(kc + 1);

        const uint32_t* A  = As + (kc & 1) * 128 * AS_STRIDE;
        const uint32_t* Bm = Bs + (kc & 1) * 32 * BS_STRIDE;
#pragma unroll
        for (int s = 0; s < 4; s++) {
            uint32_t af[4][4], bf[4][2];
#pragma unroll
            for (int mf = 0; mf < 4; mf++) {
                int r = wm + mf * 16 + g;
                af[mf][0] = A[(r)     * AS_STRIDE + s * 8 + t4];
                af[mf][1] = A[(r + 8) * AS_STRIDE + s * 8 + t4];
                af[mf][2] = A[(r)     * AS_STRIDE + s * 8 + t4 + 4];
                af[mf][3] = A[(r + 8) * AS_STRIDE + s * 8 + t4 + 4];
            }
#pragma unroll
            for (int nf = 0; nf < 4; nf++) {
                bf[nf][0] = Bm[(s * 8 + t4)     * BS_STRIDE + wn + nf * 8 + g];
                bf[nf][1] = Bm[(s * 8 + t4 + 4) * BS_STRIDE + wn + nf * 8 + g];
            }
#pragma unroll
            for (int mf = 0; mf < 4; mf++)
#pragma unroll
                for (int nf = 0; nf < 4; nf++)
                    mma1688(acc[mf][nf], af[mf], bf[nf]);
        }
        if (kc + 1 < NC) STORE((kc + 1) & 1);
        __syncthreads();
    }

    // epilogue: bias (+ optional q scale), store float2 per accumulator pair
#pragma unroll
    for (int mf = 0; mf < 4; mf++) {
        int r0 = m0 + wm + mf * 16 + g;
        int r1 = r0 + 8;
        float b0v = bias[r0], b1v = bias[r1];
        float s0 = (SCALE_ROWS > 0 && r0 < SCALE_ROWS) ? scaleVal : 1.f;
        float s1 = (SCALE_ROWS > 0 && r1 < SCALE_ROWS) ? scaleVal : 1.f;
#pragma unroll
        for (int nf = 0; nf < 4; nf++) {
            int nc = n0 + wn + nf * 8 + 2 * t4;
            float2 v0, v1;
            v0.x = (acc[mf][nf][0] + b0v) * s0;
            v0.y = (acc[mf][nf][1] + b0v) * s0;
            v1.x = (acc[mf][nf][2] + b1v) * s1;
            v1.y = (acc[mf][nf][3] + b1v) * s1;
            *(float2*)&Yb[(size_t)r0 * 1024 + nc] = v0;
            *(float2*)&Yb[(size_t)r1 * 1024 + nc] = v1;
        }
    }
}

// ===========================================================================
// Fused attention: logits -> softmax ACROSS HEADS (reference axis=1) -> AV.
// All transcendental work on the FMA pipe: polynomial exp2, Newton reciprocal.
// Output written directly in the reference's flat-reshape (scrambled) layout.
// ===========================================================================
static constexpr int ATTN_SMEM = (8192 + 4096 + 4608 + 4096 + 512) * 4; // 86016

__global__ __launch_bounds__(256, 2)
void attn_fused(const float* __restrict__ qkv, float* __restrict__ af)
{
    extern __shared__ char smraw[];
    float* sm = (float*)smraw;
    float* Qs = sm;                        // [8][32][32]  (n, d, qi)
    float* Ks = Qs + 8 * 32 * 32;          // [8][32][16]  (n, d, ki)
    float* Vs = Ks + 8 * 32 * 16;          // [8][16][36]  (n, ki, d+pad)
    float* Es = Vs + 8 * 16 * 36;          // [8][16][32]  (n, ki, qi)
    float* Ds = Es + 8 * 16 * 32;          // [16][32]     (ki, qi) recip denoms

    const int b  = blockIdx.y;
    const int q0 = blockIdx.x * 32;
    const int t  = threadIdx.x;
    const int n  = t >> 5;
    const int qi = t & 31;

    const float* qb = qkv + (size_t)b * QKV_CH * HW;

    // exp constants (packed)
    const ull LOG2E2 = dup2(1.4426950408889634f);
    const ull MAGIC2 = dup2(12582912.0f);
    const ull NMAGIC2 = dup2(-12582912.0f);
    const ull NONE2  = dup2(-1.0f);
    const ull C6 = dup2(1.5403530393381608e-4f);
    const ull C5 = dup2(1.3333558146428443e-3f);
    const ull C4 = dup2(9.618129107628477e-3f);
    const ull C3 = dup2(5.550410866482158e-2f);
    const ull C2 = dup2(2.402265069591007e-1f);
    const ull C1 = dup2(6.931471805599453e-1f);
    const ull C0 = dup2(1.0f);

    for (int i = t; i < 8192; i += 256) {
        int nn = i >> 10, dd = (i >> 5) & 31, qq = i & 31;
        Qs[i] = qb[(size_t)(nn * 32 + dd) * HW + q0 + qq];
    }

    ull acc2[16];
#pragma unroll
    for (int i = 0; i < 16; i++) acc2[i] = 0ull;

    const float*  qcol = Qs + n * 1024 + qi;
    const float4* krow = (const float4*)(Ks + n * 512);

    for (int kt = 0; kt < 64; kt++) {
        const int k0 = kt * 16;
        __syncthreads();   // protect Ks/Vs/Es/Ds reuse (covers Qs on iter 0)

        for (int i = t; i < 4096; i += 256) {
            int nn = i >> 9, dd = (i >> 4) & 31, ki = i & 15;
            Ks[i] = qb[(size_t)(256 + nn * 32 + dd) * HW + k0 + ki];
        }
        for (int i = t; i < 4096; i += 256) {
            int nn = i >> 9, dd = (i >> 4) & 31, ki = i & 15;
            Vs[(nn * 16 + ki) * 36 + dd] =
                qb[(size_t)(512 + nn * 32 + dd) * HW + k0 + ki];
        }
        __syncthreads();

        // ---- logits: packed FMA, l2[p] holds (ki=2p, 2p+1) ----
        ull l2[8];
#pragma unroll
        for (int p = 0; p < 8; p++) l2[p] = 0ull;
#pragma unroll
        for (int d = 0; d < 32; d++) {
            ull qd = dup2(qcol[d * 32]);
            float4 k0v = krow[d * 4 + 0];
            float4 k1v = krow[d * 4 + 1];
            float4 k2v = krow[d * 4 + 2];
            float4 k3v = krow[d * 4 + 3];
            fma2(l2[0], qd, pk2(k0v.x, k0v.y));
            fma2(l2[1], qd, pk2(k0v.z, k0v.w));
            fma2(l2[2], qd, pk2(k1v.x, k1v.y));
            fma2(l2[3], qd, pk2(k1v.z, k1v.w));
            fma2(l2[4], qd, pk2(k2v.x, k2v.y));
            fma2(l2[5], qd, pk2(k2v.z, k2v.w));
            fma2(l2[6], qd, pk2(k3v.x, k3v.y));
            fma2(l2[7], qd, pk2(k3v.z, k3v.w));
        }

        // ---- exp via packed polynomial 2^y (no MUFU) ----
        float e[16];
#pragma unroll
        for (int p = 0; p < 8; p++) {
            ull y  = mul2v(l2[p], LOG2E2);
            ull tt = add2v(y, MAGIC2);          // rint in low mantissa bits
            ull nn2 = add2v(tt, NMAGIC2);       // n as float
            ull f  = fma2v(nn2, NONE2, y);      // f = y - n, f in [-0.5, 0.5]
            ull pe = fma2v(C6, f, C5);
            pe = fma2v(pe, f, C4);
            pe = fma2v(pe, f, C3);
            pe = fma2v(pe, f, C2);
            pe = fma2v(pe, f, C1);
            pe = fma2v(pe, f, C0);
            uint32_t tlo, thi, plo, phi;
            asm("mov.b64 {%0,%1}, %2;" : "=r"(tlo), "=r"(thi) : "l"(tt));
            asm("mov.b64 {%0,%1}, %2;" : "=r"(plo), "=r"(phi) : "l"(pe));
            // low bits of magic are zero -> (bits<<23) == n<<23 exactly
            float elo = __int_as_float((int)((tlo << 23) + plo));
            float ehi = __int_as_float((int)((thi << 23) + phi));
            e[2 * p]     = elo;
            e[2 * p + 1] = ehi;
            Es[(n * 16 + 2 * p)     * 32 + qi] = elo;
            Es[(n * 16 + 2 * p + 1) * 32 + qi] = ehi;
        }
        __syncthreads();

        // ---- cooperative denominators: thread (n,qi) owns ki = 2n, 2n+1 ----
#pragma unroll
        for (int j = 0; j < 2; j++) {
            int ki = 2 * n + j;
            float ssum = 0.f;
#pragma unroll
            for (int nn2 = 0; nn2 < 8; nn2++)
                ssum += Es[(nn2 * 16 + ki) * 32 + qi];
            Ds[ki * 32 + qi] = frcp(ssum);
        }
        __syncthreads();

        // ---- weights @ V (packed FMA) ----
#pragma unroll
        for (int ki = 0; ki < 16; ki++) {
            float w = e[ki] * Ds[ki * 32 + qi];
            ull wd = dup2(w);
            const float4* vp = (const float4*)(Vs + (n * 16 + ki) * 36);
#pragma unroll
            for (int d4 = 0; d4 < 8; d4++) {
                float4 v = vp[d4];
                fma2(acc2[d4 * 2 + 0], wd, pk2(v.x, v.y));
                fma2(acc2[d4 * 2 + 1], wd, pk2(v.z, v.w));
            }
        }
    }

    // write in scrambled (flat-reshape) layout for the output projection GEMM
    const int q  = q0 + qi;
    const int cc = n * 32 + (q >> 5);
    const int sb = (q & 31) * 32;
    float* out = af + ((size_t)b * 256 + cc) * HW + sb;
#pragma unroll
    for (int d4 = 0; d4 < 8; d4++) {
        float4 o;
        unpk2(acc2[d4 * 2 + 0], o.x, o.y);
        unpk2(acc2[d4 * 2 + 1], o.z, o.w);
        *(float4*)&out[d4 * 4] = o;
    }
}

// ---------------------------------------------------------------------------
extern "C" void kernel_launch(void* const* d_in, const int* in_sizes, int n_in,
                              void* d_out, int out_size)
{
    const float* x      = (const float*)d_in[0];   // [8,512,32,32]
    const float* w_qkv  = (const float*)d_in[1];   // [768,512]
    const float* b_qkv  = (const float*)d_in[2];   // [768]
    const float* w_attn = (const float*)d_in[3];   // [512,256]
    const float* b_attn = (const float*)d_in[4];   // [512]
    float* out = (float*)d_out;                    // [8,512,32,32]

    void* qkvp = nullptr;
    void* afp  = nullptr;
    cudaGetSymbolAddress(&qkvp, g_qkv);
    cudaGetSymbolAddress(&afp,  g_af);

    cudaFuncSetAttribute(gemm_mma<768, 512, 256>,
                         cudaFuncAttributeMaxDynamicSharedMemorySize, GEMM_SMEM);
    cudaFuncSetAttribute(gemm_mma<512, 256, 0>,
                         cudaFuncAttributeMaxDynamicSharedMemorySize, GEMM_SMEM);
    cudaFuncSetAttribute(attn_fused,
                         cudaFuncAttributeMaxDynamicSharedMemorySize, ATTN_SMEM);

    // 1) QKV projection (tf32 mma.sync; bias; q rows scaled by 32^-0.5)
    gemm_mma<768, 512, 256><<<dim3(8, 6, BATCH), 256, GEMM_SMEM>>>(
        w_qkv, x, b_qkv, (float*)qkvp, 0.17677669529663687f);

    // 2) fused logits -> head-softmax -> AV (fp32, MUFU-free)
    attn_fused<<<dim3(32, BATCH), 256, ATTN_SMEM>>>((const float*)qkvp,
                                                    (float*)afp);

    // 3) output projection (tf32 mma.sync; bias)
    gemm_mma<512, 256, 0><<<dim3(8, 4, BATCH), 256, GEMM_SMEM>>>(
        w_attn, (const float*)afp, b_attn, out, 1.0f);
}

// round 4
// speedup vs baseline: 3.1575x; 2.3428x over previous
#include <cuda_runtime.h>
#include <cstdint>

#define BATCH 8
#define CIN   512
#define HW    1024
#define NHEAD 8
#define QKV_CH 768

// Scratch (device globals; no allocation allowed)
__device__ float g_qkv[BATCH * QKV_CH * HW];   // [b][768][1024]
__device__ float g_af [BATCH * 256   * HW];    // attention out, scrambled reshape layout

// ===========================================================================
// helpers
// ===========================================================================
__device__ __forceinline__ uint32_t f2tf32(float v) {
    uint32_t r;
    asm("cvt.rna.tf32.f32 %0, %1;" : "=r"(r) : "f"(v));
    return r;
}
__device__ __forceinline__ void mma1688(float* c, const uint32_t* a, const uint32_t* b) {
    asm volatile("mma.sync.aligned.m16n8k8.row.col.f32.tf32.tf32.f32 "
        "{%0,%1,%2,%3}, {%4,%5,%6,%7}, {%8,%9}, {%0,%1,%2,%3};"
        : "+f"(c[0]), "+f"(c[1]), "+f"(c[2]), "+f"(c[3])
        : "r"(a[0]), "r"(a[1]), "r"(a[2]), "r"(a[3]), "r"(b[0]), "r"(b[1]));
}

// packed fp32x2 (exact fp32 math at 2x pipe rate)
typedef unsigned long long ull;
__device__ __forceinline__ ull fma2v(ull a, ull b, ull c) {
    ull d; asm("fma.rn.f32x2 %0, %1, %2, %3;" : "=l"(d) : "l"(a), "l"(b), "l"(c)); return d;
}
__device__ __forceinline__ ull mul2v(ull a, ull b) {
    ull d; asm("mul.rn.f32x2 %0, %1, %2;" : "=l"(d) : "l"(a), "l"(b)); return d;
}
__device__ __forceinline__ ull add2v(ull a, ull b) {
    ull d; asm("add.rn.f32x2 %0, %1, %2;" : "=l"(d) : "l"(a), "l"(b)); return d;
}
__device__ __forceinline__ ull dup2(float v) {
    ull r; uint32_t u = __float_as_uint(v);
    asm("mov.b64 %0, {%1, %1};" : "=l"(r) : "r"(u));
    return r;
}
__device__ __forceinline__ ull pk2(float x, float y) {
    ull r; uint32_t a = __float_as_uint(x), b = __float_as_uint(y);
    asm("mov.b64 %0, {%1, %2};" : "=l"(r) : "r"(a), "r"(b));
    return r;
}
__device__ __forceinline__ void unpk2(ull v, float& x, float& y) {
    uint32_t a, b;
    asm("mov.b64 {%0, %1}, %2;" : "=r"(a), "=r"(b) : "l"(v));
    x = __uint_as_float(a); y = __uint_as_float(b);
}
// FMA-pipe reciprocal (no MUFU)
__device__ __forceinline__ float frcp(float x) {
    float r = __int_as_float(0x7EF311C3 - __float_as_int(x));
    r = r * (2.0f - x * r);
    r = r * (2.0f - x * r);
    r = r * (2.0f - x * r);
    return r;
}
// packed exp on a float pair: returns pk2(exp(x), exp(y))
__device__ __forceinline__ ull exp2pair(ull l) {
    const ull LOG2E2 = dup2(1.4426950408889634f);
    const ull MAGIC2 = dup2(12582912.0f);
    const ull NMAGIC2 = dup2(-12582912.0f);
    const ull NONE2  = dup2(-1.0f);
    ull y  = mul2v(l, LOG2E2);
    ull tt = add2v(y, MAGIC2);
    ull nn2 = add2v(tt, NMAGIC2);
    ull f  = fma2v(nn2, NONE2, y);
    ull pe = fma2v(dup2(1.5403530393381608e-4f), f, dup2(1.3333558146428443e-3f));
    pe = fma2v(pe, f, dup2(9.618129107628477e-3f));
    pe = fma2v(pe, f, dup2(5.550410866482158e-2f));
    pe = fma2v(pe, f, dup2(2.402265069591007e-1f));
    pe = fma2v(pe, f, dup2(6.931471805599453e-1f));
    pe = fma2v(pe, f, dup2(1.0f));
    uint32_t tlo, thi, plo, phi;
    asm("mov.b64 {%0,%1}, %2;" : "=r"(tlo), "=r"(thi) : "l"(tt));
    asm("mov.b64 {%0,%1}, %2;" : "=r"(plo), "=r"(phi) : "l"(pe));
    uint32_t elo = (tlo << 23) + plo;
    uint32_t ehi = (thi << 23) + phi;
    ull r;
    asm("mov.b64 %0, {%1, %2};" : "=l"(r) : "r"(elo), "r"(ehi));
    return r;
}

// ===========================================================================
// tf32 mma.sync GEMM (unchanged from round 3)
// ===========================================================================
#define AS_STRIDE 36
#define BS_STRIDE 136
static constexpr int GEMM_SMEM = (2 * 128 * AS_STRIDE + 2 * 32 * BS_STRIDE) * 4;

template<int M, int K, int SCALE_ROWS>
__global__ __launch_bounds__(256, 2)
void gemm_mma(const float* __restrict__ W, const float* __restrict__ X,
              const float* __restrict__ bias, float* __restrict__ Y,
              float scaleVal)
{
    extern __shared__ char smraw[];
    uint32_t* As = (uint32_t*)smraw;
    uint32_t* Bs = (uint32_t*)smraw + 2 * 128 * AS_STRIDE;

    const int t    = threadIdx.x;
    const int lane = t & 31;
    const int wid  = t >> 5;
    const int g    = lane >> 2;
    const int t4   = lane & 3;
    const int wm   = (wid & 1) * 64;
    const int wn   = (wid >> 1) * 32;
    const int b    = blockIdx.z;
    const int m0   = blockIdx.y * 128;
    const int n0   = blockIdx.x * 128;
    const float* Xb = X + (size_t)b * K * 1024;
    float*       Yb = Y + (size_t)b * M * 1024;

    const int am = t >> 3;
    const int ak = (t & 7) * 4;
    const int bk = t >> 5;
    const int bn = (t & 31) * 4;

    float4 aw[4], bw[4];
    float acc[4][4][4];
#pragma unroll
    for (int i = 0; i < 4; i++)
#pragma unroll
        for (int j = 0; j < 4; j++)
#pragma unroll
            for (int q = 0; q < 4; q++) acc[i][j][q] = 0.f;

    auto LOADR = [&](int kc) {
#pragma unroll
        for (int c = 0; c < 4; c++)
            aw[c] = *(const float4*)&W[(size_t)(m0 + am + c * 32) * K + kc * 32 + ak];
#pragma unroll
        for (int c = 0; c < 4; c++)
            bw[c] = *(const float4*)&Xb[(size_t)(kc * 32 + bk + c * 8) * 1024 + n0 + bn];
    };
    auto STORE = [&](int st) {
        uint32_t* A  = As + st * 128 * AS_STRIDE;
        uint32_t* Bm = Bs + st * 32 * BS_STRIDE;
#pragma unroll
        for (int c = 0; c < 4; c++) {
            uint4 v;
            v.x = f2tf32(aw[c].x); v.y = f2tf32(aw[c].y);
            v.z = f2tf32(aw[c].z); v.w = f2tf32(aw[c].w);
            *(uint4*)&A[(am + c * 32) * AS_STRIDE + ak] = v;
        }
#pragma unroll
        for (int c = 0; c < 4; c++) {
            uint4 v;
            v.x = f2tf32(bw[c].x); v.y = f2tf32(bw[c].y);
            v.z = f2tf32(bw[c].z); v.w = f2tf32(bw[c].w);
            *(uint4*)&Bm[(bk + c * 8) * BS_STRIDE + bn] = v;
        }
    };

    const int NC = K / 32;
    LOADR(0);
    STORE(0);
    __syncthreads();

    for (int kc = 0; kc < NC; kc++) {
        if (kc + 1 < NC) LOADR(kc + 1);

        const uint32_t* A  = As + (kc & 1) * 128 * AS_STRIDE;
        const uint32_t* Bm = Bs + (kc & 1) * 32 * BS_STRIDE;
#pragma unroll
        for (int s = 0; s < 4; s++) {
            uint32_t af[4][4], bf[4][2];
#pragma unroll
            for (int mf = 0; mf < 4; mf++) {
                int r = wm + mf * 16 + g;
                af[mf][0] = A[(r)     * AS_STRIDE + s * 8 + t4];
                af[mf][1] = A[(r + 8) * AS_STRIDE + s * 8 + t4];
                af[mf][2] = A[(r)     * AS_STRIDE + s * 8 + t4 + 4];
                af[mf][3] = A[(r + 8) * AS_STRIDE + s * 8 + t4 + 4];
            }
#pragma unroll
            for (int nf = 0; nf < 4; nf++) {
                bf[nf][0] = Bm[(s * 8 + t4)     * BS_STRIDE + wn + nf * 8 + g];
                bf[nf][1] = Bm[(s * 8 + t4 + 4) * BS_STRIDE + wn + nf * 8 + g];
            }
#pragma unroll
            for (int mf = 0; mf < 4; mf++)
#pragma unroll
                for (int nf = 0; nf < 4; nf++)
                    mma1688(acc[mf][nf], af[mf], bf[nf]);
        }
        if (kc + 1 < NC) STORE((kc + 1) & 1);
        __syncthreads();
    }

#pragma unroll
    for (int mf = 0; mf < 4; mf++) {
        int r0 = m0 + wm + mf * 16 + g;
        int r1 = r0 + 8;
        float b0v = bias[r0], b1v = bias[r1];
        float s0 = (SCALE_ROWS > 0 && r0 < SCALE_ROWS) ? scaleVal : 1.f;
        float s1 = (SCALE_ROWS > 0 && r1 < SCALE_ROWS) ? scaleVal : 1.f;
#pragma unroll
        for (int nf = 0; nf < 4; nf++) {
            int nc = n0 + wn + nf * 8 + 2 * t4;
            float2 v0, v1;
            v0.x = (acc[mf][nf][0] + b0v) * s0;
            v0.y = (acc[mf][nf][1] + b0v) * s0;
            v1.x = (acc[mf][nf][2] + b1v) * s1;
            v1.y = (acc[mf][nf][3] + b1v) * s1;
            *(float2*)&Yb[(size_t)r0 * 1024 + nc] = v0;
            *(float2*)&Yb[(size_t)r1 * 1024 + nc] = v1;
        }
    }
}

// ===========================================================================
// Tensor-core fused attention. Block = (b, 32-query tile); warp = head.
// Per 32-wide k-tile: S = Q^T K (tf32 mma) -> exp in-register -> E stored
// transposed Es[n][kpos][q] -> cross-head denom + Newton recip + rescale to
// tf32 in one smem pass -> O += W V via mma with roles swapped (A=V natural
// [d][kpos], B=W from Es). O accumulated in registers across all 64... 32
// k-tiles; epilogue writes the reference's flat-reshape (scrambled) layout.
// Softmax is across the 8 HEADS (reference axis=1).
// ===========================================================================
#define KSTR 36                // K/V smem row stride (floats)
#define ESTR 36                // Es row stride (kpos rows, q cols)
static constexpr int ATTN_SMEM =
    (256 * KSTR + 256 * KSTR + 8 * 32 * ESTR) * 4;   // 110592 B

__global__ __launch_bounds__(256, 2)
void attn_mma(const float* __restrict__ qkv, float* __restrict__ af)
{
    extern __shared__ char smraw[];
    float* Ks = (float*)smraw;            // [256 rows = n*32+d][KSTR] cols = kpos (tf32 bits)
    float* Vs = Ks + 256 * KSTR;          // [256 rows = n*32+d][KSTR] cols = kpos (tf32 bits)
    float* Es = Vs + 256 * KSTR;          // [8][32 kpos][ESTR] cols = q

    const int b    = blockIdx.y;
    const int qt   = blockIdx.x;
    const int q0   = qt * 32;
    const int t    = threadIdx.x;
    const int lane = t & 31;
    const int n    = t >> 5;              // warp = head
    const int g    = lane >> 2;
    const int t4   = lane & 3;

    const float* qb = qkv + (size_t)b * QKV_CH * HW;
    float* EsN = Es + n * 32 * ESTR;

    // ---- preload Q A-fragments (m = q (32), k = d (32)); reused 32 k-tiles --
    uint32_t qa[2][4][4];
#pragma unroll
    for (int mf = 0; mf < 2; mf++)
#pragma unroll
        for (int ks = 0; ks < 4; ks++) {
            int d0 = ks * 8 + t4;
            int qq = q0 + mf * 16 + g;
            const float* r0 = qb + (size_t)(n * 32 + d0) * HW;
            const float* r1 = qb + (size_t)(n * 32 + d0 + 4) * HW;
            qa[mf][ks][0] = f2tf32(r0[qq]);
            qa[mf][ks][1] = f2tf32(r0[qq + 8]);
            qa[mf][ks][2] = f2tf32(r1[qq]);
            qa[mf][ks][3] = f2tf32(r1[qq + 8]);
        }

    float oacc[2][4][4];                  // m = d (2 frags), n = q (4 frags)
#pragma unroll
    for (int i = 0; i < 2; i++)
#pragma unroll
        for (int j = 0; j < 4; j++)
#pragma unroll
            for (int q = 0; q < 4; q++) oacc[i][j][q] = 0.f;

    for (int kt = 0; kt < 32; kt++) {
        const int k0 = kt * 32;
        __syncthreads();   // Ks/Vs/Es safe to overwrite (prev AV done)

        // ---- stage K (qkv rows 256..511) and V (rows 512..767), tf32 ----
#pragma unroll
        for (int c = 0; c < 8; c++) {
            int row = c * 32 + (t >> 3);
            int col = (t & 7) * 4;
            float4 v = *(const float4*)&qb[(size_t)(256 + row) * HW + k0 + col];
            uint4 tv;
            tv.x = f2tf32(v.x); tv.y = f2tf32(v.y);
            tv.z = f2tf32(v.z); tv.w = f2tf32(v.w);
            *(uint4*)&Ks[row * KSTR + col] = tv;
        }
#pragma unroll
        for (int c = 0; c < 8; c++) {
            int row = c * 32 + (t >> 3);
            int col = (t & 7) * 4;
            float4 v = *(const float4*)&qb[(size_t)(512 + row) * HW + k0 + col];
            uint4 tv;
            tv.x = f2tf32(v.x); tv.y = f2tf32(v.y);
            tv.z = f2tf32(v.z); tv.w = f2tf32(v.w);
            *(uint4*)&Vs[row * KSTR + col] = tv;
        }
        __syncthreads();

        // ---- S = Q^T K, exp in-register, store E transposed ----
        const uint32_t* KsN = (const uint32_t*)(Ks + n * 32 * KSTR);
#pragma unroll
        for (int nf = 0; nf < 4; nf++) {
            float sacc[2][4];
#pragma unroll
            for (int mf = 0; mf < 2; mf++)
#pragma unroll
                for (int q = 0; q < 4; q++) sacc[mf][q] = 0.f;
#pragma unroll
            for (int ks = 0; ks < 4; ks++) {
                uint32_t bf[2];
                bf[0] = KsN[(ks * 8 + t4)     * KSTR + nf * 8 + g];
                bf[1] = KsN[(ks * 8 + t4 + 4) * KSTR + nf * 8 + g];
                mma1688(sacc[0], qa[0][ks], bf);
                mma1688(sacc[1], qa[1][ks], bf);
            }
            // exp + transposed store: kpos = 8nf + 2t4 (+1), q = 16mf + g (+8)
#pragma unroll
            for (int mf = 0; mf < 2; mf++) {
                ull e01 = exp2pair(pk2(sacc[mf][0], sacc[mf][1]));
                ull e23 = exp2pair(pk2(sacc[mf][2], sacc[mf][3]));
                float e0, e1, e2, e3;
                unpk2(e01, e0, e1);
                unpk2(e23, e2, e3);
                float* base = EsN + (nf * 8 + 2 * t4) * ESTR + mf * 16 + g;
                base[0]        = e0;
                base[ESTR]     = e1;
                base[8]        = e2;
                base[ESTR + 8] = e3;
            }
        }
        __syncthreads();

        // ---- denom across heads + recip + rescale Es in place (to tf32) ----
#pragma unroll
        for (int j = 0; j < 2; j++) {
            int P  = t * 2 + j;              // 512 q-pair slots
            int kp = P >> 4;
            int qp = (P & 15) * 2;
            float* e0p = Es + kp * ESTR + qp;
            ull e[8];
            ull s = 0ull;
#pragma unroll
            for (int n2 = 0; n2 < 8; n2++) {
                e[n2] = *(ull*)(e0p + n2 * (32 * ESTR));
                s = add2v(s, e[n2]);
            }
            float slo, shi;
            unpk2(s, slo, shi);
            ull r = pk2(frcp(slo), frcp(shi));
#pragma unroll
            for (int n2 = 0; n2 < 8; n2++) {
                ull w = mul2v(e[n2], r);
                float wl, wh;
                unpk2(w, wl, wh);
                uint2 wt;
                wt.x = f2tf32(wl);
                wt.y = f2tf32(wh);
                *(uint2*)(e0p + n2 * (32 * ESTR)) = wt;
            }
        }
        __syncthreads();

        // ---- O += W V   (m = d, n = q, k = kpos) ----
        const uint32_t* VsN = (const uint32_t*)(Vs + n * 32 * KSTR);
        const uint32_t* WsN = (const uint32_t*)EsN;
#pragma unroll
        for (int ks = 0; ks < 4; ks++) {
            uint32_t bf[4][2], afr[2][4];
#pragma unroll
            for (int nf = 0; nf < 4; nf++) {
                bf[nf][0] = WsN[(ks * 8 + t4)     * ESTR + nf * 8 + g];
                bf[nf][1] = WsN[(ks * 8 + t4 + 4) * ESTR + nf * 8 + g];
            }
#pragma unroll
            for (int mf = 0; mf < 2; mf++) {
                int d0 = mf * 16 + g;
                afr[mf][0] = VsN[(d0)     * KSTR + ks * 8 + t4];
                afr[mf][1] = VsN[(d0 + 8) * KSTR + ks * 8 + t4];
                afr[mf][2] = VsN[(d0)     * KSTR + ks * 8 + t4 + 4];
                afr[mf][3] = VsN[(d0 + 8) * KSTR + ks * 8 + t4 + 4];
            }
#pragma unroll
            for (int mf = 0; mf < 2; mf++)
#pragma unroll
                for (int nf = 0; nf < 4; nf++)
                    mma1688(oacc[mf][nf], afr[mf], bf[nf]);
        }
    }

    // ---- epilogue: scrambled flat-reshape layout ----
    // af row = b*256 + n*32 + qt; col = qi*32 + d
    float* ob = af + ((size_t)(b * 256 + n * 32 + qt)) * 1024;
#pragma unroll
    for (int mf = 0; mf < 2; mf++)
#pragma unroll
        for (int nf = 0; nf < 4; nf++) {
            int d = 16 * mf + g;
            int q = 8 * nf + 2 * t4;
            ob[q * 32 + d]           = oacc[mf][nf][0];
            ob[(q + 1) * 32 + d]     = oacc[mf][nf][1];
            ob[q * 32 + d + 8]       = oacc[mf][nf][2];
            ob[(q + 1) * 32 + d + 8] = oacc[mf][nf][3];
        }
}

// ---------------------------------------------------------------------------
extern "C" void kernel_launch(void* const* d_in, const int* in_sizes, int n_in,
                              void* d_out, int out_size)
{
    const float* x      = (const float*)d_in[0];   // [8,512,32,32]
    const float* w_qkv  = (const float*)d_in[1];   // [768,512]
    const float* b_qkv  = (const float*)d_in[2];   // [768]
    const float* w_attn = (const float*)d_in[3];   // [512,256]
    const float* b_attn = (const float*)d_in[4];   // [512]
    float* out = (float*)d_out;                    // [8,512,32,32]

    void* qkvp = nullptr;
    void* afp  = nullptr;
    cudaGetSymbolAddress(&qkvp, g_qkv);
    cudaGetSymbolAddress(&afp,  g_af);

    cudaFuncSetAttribute(gemm_mma<768, 512, 256>,
                         cudaFuncAttributeMaxDynamicSharedMemorySize, GEMM_SMEM);
    cudaFuncSetAttribute(gemm_mma<512, 256, 0>,
                         cudaFuncAttributeMaxDynamicSharedMemorySize, GEMM_SMEM);
    cudaFuncSetAttribute(attn_mma,
                         cudaFuncAttributeMaxDynamicSharedMemorySize, ATTN_SMEM);

    // 1) QKV projection (tf32 mma.sync; bias; q rows scaled by 32^-0.5)
    gemm_mma<768, 512, 256><<<dim3(8, 6, BATCH), 256, GEMM_SMEM>>>(
        w_qkv, x, b_qkv, (float*)qkvp, 0.17677669529663687f);

    // 2) tensor-core fused attention (head-softmax)
    attn_mma<<<dim3(32, BATCH), 256, ATTN_SMEM>>>((const float*)qkvp,
                                                  (float*)afp);

    // 3) output projection (tf32 mma.sync; bias)
    gemm_mma<512, 256, 0><<<dim3(8, 4, BATCH), 256, GEMM_SMEM>>>(
        w_attn, (const float*)afp, b_attn, out, 1.0f);
}

// round 5
// speedup vs baseline: 4.8927x; 1.5496x over previous
#include <cuda_runtime.h>
#include <cuda_fp16.h>
#include <cstdint>

#define BATCH 8
#define HW    1024
#define QKV_CH 768

// Scratch (device globals; no allocation allowed)
__device__ float g_qkv[BATCH * QKV_CH * HW];   // [b][768][1024]
__device__ float g_af [BATCH * 256   * HW];    // attention out, scrambled reshape layout

// ===========================================================================
// helpers
// ===========================================================================
__device__ __forceinline__ uint32_t smem_u32(const void* p) {
    uint32_t a;
    asm("{ .reg .u64 t; cvta.to.shared.u64 t, %1; cvt.u32.u64 %0, t; }"
        : "=r"(a) : "l"(p));
    return a;
}
__device__ __forceinline__ void mma16816(float* c, const uint32_t* a, const uint32_t* b) {
    asm volatile("mma.sync.aligned.m16n8k16.row.col.f32.f16.f16.f32 "
        "{%0,%1,%2,%3}, {%4,%5,%6,%7}, {%8,%9}, {%0,%1,%2,%3};"
        : "+f"(c[0]), "+f"(c[1]), "+f"(c[2]), "+f"(c[3])
        : "r"(a[0]), "r"(a[1]), "r"(a[2]), "r"(a[3]), "r"(b[0]), "r"(b[1]));
}
__device__ __forceinline__ void ldsm_x4(uint32_t* r, uint32_t addr) {
    asm volatile("ldmatrix.sync.aligned.m8n8.x4.shared.b16 {%0,%1,%2,%3}, [%4];"
        : "=r"(r[0]), "=r"(r[1]), "=r"(r[2]), "=r"(r[3]) : "r"(addr));
}
__device__ __forceinline__ void ldsm_x4t(uint32_t* r, uint32_t addr) {
    asm volatile("ldmatrix.sync.aligned.m8n8.x4.trans.shared.b16 {%0,%1,%2,%3}, [%4];"
        : "=r"(r[0]), "=r"(r[1]), "=r"(r[2]), "=r"(r[3]) : "r"(addr));
}
__device__ __forceinline__ uint32_t pack_h2(float lo, float hi) {
    __half2 h = __floats2half2_rn(lo, hi);
    return *reinterpret_cast<uint32_t*>(&h);
}
__device__ __forceinline__ float2 h2f2(uint32_t u) {
    __half2 h = *reinterpret_cast<__half2*>(&u);
    return __half22float2(h);
}

// packed fp32x2 (exact fp32 math at 2x pipe rate)
typedef unsigned long long ull;
__device__ __forceinline__ ull fma2v(ull a, ull b, ull c) {
    ull d; asm("fma.rn.f32x2 %0, %1, %2, %3;" : "=l"(d) : "l"(a), "l"(b), "l"(c)); return d;
}
__device__ __forceinline__ ull mul2v(ull a, ull b) {
    ull d; asm("mul.rn.f32x2 %0, %1, %2;" : "=l"(d) : "l"(a), "l"(b)); return d;
}
__device__ __forceinline__ ull add2v(ull a, ull b) {
    ull d; asm("add.rn.f32x2 %0, %1, %2;" : "=l"(d) : "l"(a), "l"(b)); return d;
}
__device__ __forceinline__ ull dup2(float v) {
    ull r; uint32_t u = __float_as_uint(v);
    asm("mov.b64 %0, {%1, %1};" : "=l"(r) : "r"(u));
    return r;
}
__device__ __forceinline__ ull pk2(float x, float y) {
    ull r; uint32_t a = __float_as_uint(x), b = __float_as_uint(y);
    asm("mov.b64 %0, {%1, %2};" : "=l"(r) : "r"(a), "r"(b));
    return r;
}
// FMA-pipe reciprocal (no MUFU)
__device__ __forceinline__ float frcp(float x) {
    float r = __int_as_float(0x7EF311C3 - __float_as_int(x));
    r = r * (2.0f - x * r);
    r = r * (2.0f - x * r);
    r = r * (2.0f - x * r);
    return r;
}
// packed exp on a float pair -> two floats
__device__ __forceinline__ void exp2pairf(ull l, float& elo, float& ehi) {
    const ull LOG2E2 = dup2(1.4426950408889634f);
    const ull MAGIC2 = dup2(12582912.0f);
    const ull NMAGIC2 = dup2(-12582912.0f);
    const ull NONE2  = dup2(-1.0f);
    ull y  = mul2v(l, LOG2E2);
    ull tt = add2v(y, MAGIC2);
    ull nn2 = add2v(tt, NMAGIC2);
    ull f  = fma2v(nn2, NONE2, y);
    ull pe = fma2v(dup2(9.6183290401232e-3f), f, dup2(5.550410866482158e-2f));
    pe = fma2v(pe, f, dup2(2.402265069591007e-1f));
    pe = fma2v(pe, f, dup2(6.931471805599453e-1f));
    pe = fma2v(pe, f, dup2(1.0f));
    uint32_t tlo, thi, plo, phi;
    asm("mov.b64 {%0,%1}, %2;" : "=r"(tlo), "=r"(thi) : "l"(tt));
    asm("mov.b64 {%0,%1}, %2;" : "=r"(plo), "=r"(phi) : "l"(pe));
    elo = __int_as_float((int)((tlo << 23) + plo));
    ehi = __int_as_float((int)((thi << 23) + phi));
}

// ===========================================================================
// fp16 mma.sync GEMM: Y[b][m][n] = sum_k W[m][k] * X[b][k][n] + bias[m]
// rows m < SCALE_ROWS scaled by scaleVal (q-scaling).
// CTA tile 128x128, BK=32, 8 warps (2m x 4n), warp tile 64x32, m16n8k16.
// As: [128 m][40 halves] (80B rows), Bs: [32 k][136 halves] (272B rows).
// Fragments via ldmatrix (A non-trans, B trans); double-buffered.
// ===========================================================================
static constexpr int ASZ = 128 * 80;            // 10240 B per A buffer
static constexpr int BSZ = 32 * 272;            // 8704 B per B buffer
static constexpr int GEMM_SMEM = 2 * (ASZ + BSZ);  // 37888 B

template<int M, int K, int SCALE_ROWS>
__global__ __launch_bounds__(256, 2)
void gemm_mma(const float* __restrict__ W, const float* __restrict__ X,
              const float* __restrict__ bias, float* __restrict__ Y,
              float scaleVal)
{
    extern __shared__ char smraw[];
    const uint32_t smb = smem_u32(smraw);

    const int t    = threadIdx.x;
    const int lane = t & 31;
    const int wid  = t >> 5;
    const int g    = lane >> 2;
    const int t4   = lane & 3;
    const int wm   = (wid & 1) * 64;
    const int wn   = (wid >> 1) * 32;
    const int b    = blockIdx.z;
    const int m0   = blockIdx.y * 128;
    const int n0   = blockIdx.x * 128;
    const float* Xb = X + (size_t)b * K * 1024;
    float*       Yb = Y + (size_t)b * M * 1024;

    // ldmatrix lane geometry (f1: j&1 -> row+8, j>>1 -> col+8)
    const int r16 = lane & 15;
    const int c8  = (lane >> 4) * 8;
    const uint32_t aAddr = smb + (wm + r16) * 80 + c8 * 2;
    const uint32_t bAddr = smb + 2 * ASZ + r16 * 272 + (wn + c8) * 2;

    // staging coords
    const int am = t >> 3;         // + c*32 -> m 0..127
    const int ak = (t & 7) * 4;    // k quad
    const int bk = t >> 5;         // + c*8  -> k 0..31
    const int bn = (t & 31) * 4;   // n quad

    float4 aw[4], bw[4];
    float acc[4][4][4];
#pragma unroll
    for (int i = 0; i < 4; i++)
#pragma unroll
        for (int j = 0; j < 4; j++)
#pragma unroll
            for (int q = 0; q < 4; q++) acc[i][j][q] = 0.f;

    auto LOADR = [&](int kc) {
#pragma unroll
        for (int c = 0; c < 4; c++)
            aw[c] = *(const float4*)&W[(size_t)(m0 + am + c * 32) * K + kc * 32 + ak];
#pragma unroll
        for (int c = 0; c < 4; c++)
            bw[c] = *(const float4*)&Xb[(size_t)(kc * 32 + bk + c * 8) * 1024 + n0 + bn];
    };
    auto STORE = [&](int st) {
        char* A  = smraw + st * ASZ;
        char* Bm = smraw + 2 * ASZ + st * BSZ;
#pragma unroll
        for (int c = 0; c < 4; c++) {
            uint2 v;
            v.x = pack_h2(aw[c].x, aw[c].y);
            v.y = pack_h2(aw[c].z, aw[c].w);
            *(uint2*)(A + (am + c * 32) * 80 + ak * 2) = v;
        }
#pragma unroll
        for (int c = 0; c < 4; c++) {
            uint2 v;
            v.x = pack_h2(bw[c].x, bw[c].y);
            v.y = pack_h2(bw[c].z, bw[c].w);
            *(uint2*)(Bm + (bk + c * 8) * 272 + bn * 2) = v;
        }
    };

    const int NC = K / 32;
    LOADR(0);
    STORE(0);
    __syncthreads();

    for (int kc = 0; kc < NC; kc++) {
        if (kc + 1 < NC) LOADR(kc + 1);

        const uint32_t aB = aAddr + (kc & 1) * ASZ;
        const uint32_t bB = bAddr + (kc & 1) * BSZ;
#pragma unroll
        for (int s = 0; s < 2; s++) {
            uint32_t afr[4][4], bfr[2][4];
#pragma unroll
            for (int mf = 0; mf < 4; mf++)
                ldsm_x4(afr[mf], aB + mf * 16 * 80 + s * 32);
#pragma unroll
            for (int np = 0; np < 2; np++)
                ldsm_x4t(bfr[np], bB + np * 32 + s * 16 * 272);
#pragma unroll
            for (int mf = 0; mf < 4; mf++)
#pragma unroll
                for (int np = 0; np < 2; np++) {
                    mma16816(acc[mf][2 * np],     afr[mf], bfr[np] + 0);
                    mma16816(acc[mf][2 * np + 1], afr[mf], bfr[np] + 2);
                }
        }
        if (kc + 1 < NC) STORE((kc + 1) & 1);
        __syncthreads();
    }

    // epilogue: bias (+ optional q scale)
#pragma unroll
    for (int mf = 0; mf < 4; mf++) {
        int r0 = m0 + wm + mf * 16 + g;
        int r1 = r0 + 8;
        float b0v = bias[r0], b1v = bias[r1];
        float s0 = (SCALE_ROWS > 0 && r0 < SCALE_ROWS) ? scaleVal : 1.f;
        float s1 = (SCALE_ROWS > 0 && r1 < SCALE_ROWS) ? scaleVal : 1.f;
#pragma unroll
        for (int nf = 0; nf < 4; nf++) {
            int nc = n0 + wn + nf * 8 + 2 * t4;
            float2 v0, v1;
            v0.x = (acc[mf][nf][0] + b0v) * s0;
            v0.y = (acc[mf][nf][1] + b0v) * s0;
            v1.x = (acc[mf][nf][2] + b1v) * s1;
            v1.y = (acc[mf][nf][3] + b1v) * s1;
            *(float2*)&Yb[(size_t)r0 * 1024 + nc] = v0;
            *(float2*)&Yb[(size_t)r1 * 1024 + nc] = v1;
        }
    }
}

// ===========================================================================
// fp16 tensor-core fused attention. Block = (b, 32-q tile); warp = head.
// Ks/Vs: [256 rows = n*32+d][40 halves] (kpos cols). Es: per head [32 q][40]
// (kpos cols). S = Q^T K (A=Q regs, B=K ldmatrix.trans); exp in-register ->
// Es as fp16 pairs (conflict-free STS.32); cross-head denom + Newton recip
// rescale; O += V W (A=V ldmatrix, B=Es ldmatrix non-trans). Softmax is
// across the 8 HEADS (reference axis=1). Output in scrambled reshape layout.
// ===========================================================================
static constexpr int KS_OFF = 0;
static constexpr int VS_OFF = 20480;
static constexpr int ES_OFF = 40960;
static constexpr int ATTN_SMEM = 61440;

__global__ __launch_bounds__(256, 2)
void attn_mma(const float* __restrict__ qkv, float* __restrict__ af)
{
    extern __shared__ char smraw[];
    const uint32_t smb = smem_u32(smraw);
    __half* KsH = (__half*)(smraw + KS_OFF);
    __half* VsH = (__half*)(smraw + VS_OFF);
    __half* EsH = (__half*)(smraw + ES_OFF);

    const int b    = blockIdx.y;
    const int qt   = blockIdx.x;
    const int q0   = qt * 32;
    const int t    = threadIdx.x;
    const int lane = t & 31;
    const int n    = t >> 5;              // warp = head
    const int g    = lane >> 2;
    const int t4   = lane & 3;

    // ldmatrix lane geometry
    const int r16 = lane & 15;            // f1 row
    const int c8  = (lane >> 4) * 8;      // f1 col
    const int r2  = (lane & 7) + (lane >> 4) * 8;   // f2 row (q)
    const int c2  = ((lane >> 3) & 1) * 8;          // f2 col (kpos)

    const float* qb = qkv + (size_t)b * QKV_CH * HW;

    // ---- preload Q A-fragments as fp16 (reused for all 32 k-tiles) ----
    uint32_t qa[2][2][4];
    {
        const int qg = q0 + g;
#pragma unroll
        for (int mf = 0; mf < 2; mf++)
#pragma unroll
            for (int s = 0; s < 2; s++) {
                int d0 = s * 16 + 2 * t4;
                const float* ra = qb + (size_t)(n * 32 + d0) * HW;
                const float* rb = qb + (size_t)(n * 32 + d0 + 1) * HW;
                const float* rc = qb + (size_t)(n * 32 + d0 + 8) * HW;
                const float* rd = qb + (size_t)(n * 32 + d0 + 9) * HW;
                int qq = qg + mf * 16;
                qa[mf][s][0] = pack_h2(ra[qq],     rb[qq]);
                qa[mf][s][1] = pack_h2(ra[qq + 8], rb[qq + 8]);
                qa[mf][s][2] = pack_h2(rc[qq],     rd[qq]);
                qa[mf][s][3] = pack_h2(rc[qq + 8], rd[qq + 8]);
            }
    }

    float oacc[2][4][4];
#pragma unroll
    for (int i = 0; i < 2; i++)
#pragma unroll
        for (int j = 0; j < 4; j++)
#pragma unroll
            for (int q = 0; q < 4; q++) oacc[i][j][q] = 0.f;

    // smem addr bases for ldmatrix
    const uint32_t sbK = smb + KS_OFF + ((n * 32 + r16) * 40 + c8) * 2;      // +s*16*80 +np*32
    const uint32_t sbV = smb + VS_OFF + ((n * 32 + r16) * 40 + c8) * 2;      // +mf*16*80 +ks*32
    const uint32_t sbE = smb + ES_OFF + ((n * 32 + r2) * 40 + c2) * 2;       // +np*16*80 +ks*32

    for (int kt = 0; kt < 32; kt++) {
        const int k0 = kt * 32;
        __syncthreads();   // prev AV done; Ks/Vs/Es reusable

        // ---- stage K (rows 256..511) and V (rows 512..767) as fp16 ----
        {
            const int row = t >> 3;
            const int col = (t & 7) * 4;
#pragma unroll
            for (int c = 0; c < 8; c++) {
                int rr = c * 32 + row;
                float4 v = *(const float4*)&qb[(size_t)(256 + rr) * HW + k0 + col];
                uint2 p;
                p.x = pack_h2(v.x, v.y);
                p.y = pack_h2(v.z, v.w);
                *(uint2*)(KsH + rr * 40 + col) = p;
            }
#pragma unroll
            for (int c = 0; c < 8; c++) {
                int rr = c * 32 + row;
                float4 v = *(const float4*)&qb[(size_t)(512 + rr) * HW + k0 + col];
                uint2 p;
                p.x = pack_h2(v.x, v.y);
                p.y = pack_h2(v.z, v.w);
                *(uint2*)(VsH + rr * 40 + col) = p;
            }
        }
        __syncthreads();

        // ---- S = Q^T K -> exp -> Es (fp16) ----
        __half* EsN = EsH + n * 32 * 40;
#pragma unroll
        for (int np = 0; np < 2; np++) {
            float sacc[2][2][4];
#pragma unroll
            for (int mf = 0; mf < 2; mf++)
#pragma unroll
                for (int nn = 0; nn < 2; nn++)
#pragma unroll
                    for (int q = 0; q < 4; q++) sacc[mf][nn][q] = 0.f;
#pragma unroll
            for (int s = 0; s < 2; s++) {
                uint32_t bk[4];
                ldsm_x4t(bk, sbK + s * 16 * 80 + np * 32);
#pragma unroll
                for (int mf = 0; mf < 2; mf++) {
                    mma16816(sacc[mf][0], qa[mf][s], bk + 0);
                    mma16816(sacc[mf][1], qa[mf][s], bk + 2);
                }
            }
#pragma unroll
            for (int mf = 0; mf < 2; mf++)
#pragma unroll
                for (int nn = 0; nn < 2; nn++) {
                    int kp = (np * 2 + nn) * 8 + 2 * t4;
                    int qr = mf * 16 + g;
                    float e0, e1, e2, e3;
                    exp2pairf(pk2(sacc[mf][nn][0], sacc[mf][nn][1]), e0, e1);
                    exp2pairf(pk2(sacc[mf][nn][2], sacc[mf][nn][3]), e2, e3);
                    *(uint32_t*)(EsN + qr * 40 + kp)       = pack_h2(e0, e1);
                    *(uint32_t*)(EsN + (qr + 8) * 40 + kp) = pack_h2(e2, e3);
                }
        }
        __syncthreads();

        // ---- cross-head denominators + Newton recip + rescale (fp16) ----
#pragma unroll
        for (int j = 0; j < 2; j++) {
            int P  = (t << 1) | j;           // 512 (q, kpos-pair) slots
            int qr = P >> 4;
            int kp = (P & 15) << 1;
            __half* base = EsH + qr * 40 + kp;
            uint32_t ev[8];
            float sx = 0.f, sy = 0.f;
#pragma unroll
            for (int n2 = 0; n2 < 8; n2++) {
                ev[n2] = *(uint32_t*)(base + n2 * (32 * 40));
                float2 f = h2f2(ev[n2]);
                sx += f.x; sy += f.y;
            }
            float rx = frcp(sx), ry = frcp(sy);
#pragma unroll
            for (int n2 = 0; n2 < 8; n2++) {
                float2 f = h2f2(ev[n2]);
                *(uint32_t*)(base + n2 * (32 * 40)) = pack_h2(f.x * rx, f.y * ry);
            }
        }
        __syncthreads();

        // ---- O += V W   (m = d, n = q, k = kpos) ----
#pragma unroll
        for (int ks = 0; ks < 2; ks++) {
            uint32_t va[2][4], wb[2][4];
            ldsm_x4(va[0], sbV + ks * 32);
            ldsm_x4(va[1], sbV + 16 * 80 + ks * 32);
            ldsm_x4(wb[0], sbE + ks * 32);
            ldsm_x4(wb[1], sbE + 16 * 80 + ks * 32);
#pragma unroll
            for (int mf = 0; mf < 2; mf++)
#pragma unroll
                for (int np = 0; np < 2; np++) {
                    mma16816(oacc[mf][2 * np],     va[mf], wb[np] + 0);
                    mma16816(oacc[mf][2 * np + 1], va[mf], wb[np] + 2);
                }
        }
    }

    // ---- epilogue: scrambled flat-reshape layout ----
    float* ob = af + ((size_t)(b * 256 + n * 32 + qt)) * 1024;
#pragma unroll
    for (int mf = 0; mf < 2; mf++)
#pragma unroll
        for (int nf = 0; nf < 4; nf++) {
            int d = 16 * mf + g;
            int q = 8 * nf + 2 * t4;
            ob[q * 32 + d]           = oacc[mf][nf][0];
            ob[(q + 1) * 32 + d]     = oacc[mf][nf][1];
            ob[q * 32 + d + 8]       = oacc[mf][nf][2];
            ob[(q + 1) * 32 + d + 8] = oacc[mf][nf][3];
        }
}

// ---------------------------------------------------------------------------
extern "C" void kernel_launch(void* const* d_in, const int* in_sizes, int n_in,
                              void* d_out, int out_size)
{
    const float* x      = (const float*)d_in[0];   // [8,512,32,32]
    const float* w_qkv  = (const float*)d_in[1];   // [768,512]
    const float* b_qkv  = (const float*)d_in[2];   // [768]
    const float* w_attn = (const float*)d_in[3];   // [512,256]
    const float* b_attn = (const float*)d_in[4];   // [512]
    float* out = (float*)d_out;                    // [8,512,32,32]

    void* qkvp = nullptr;
    void* afp  = nullptr;
    cudaGetSymbolAddress(&qkvp, g_qkv);
    cudaGetSymbolAddress(&afp,  g_af);

    cudaFuncSetAttribute(gemm_mma<768, 512, 256>,
                         cudaFuncAttributeMaxDynamicSharedMemorySize, GEMM_SMEM);
    cudaFuncSetAttribute(gemm_mma<512, 256, 0>,
                         cudaFuncAttributeMaxDynamicSharedMemorySize, GEMM_SMEM);
    cudaFuncSetAttribute(attn_mma,
                         cudaFuncAttributeMaxDynamicSharedMemorySize, ATTN_SMEM);

    // 1) QKV projection (fp16 mma; bias; q rows scaled by 32^-0.5)
    gemm_mma<768, 512, 256><<<dim3(8, 6, BATCH), 256, GEMM_SMEM>>>(
        w_qkv, x, b_qkv, (float*)qkvp, 0.17677669529663687f);

    // 2) fp16 tensor-core fused attention (head-softmax)
    attn_mma<<<dim3(32, BATCH), 256, ATTN_SMEM>>>((const float*)qkvp,
                                                  (float*)afp);

    // 3) output projection (fp16 mma; bias)
    gemm_mma<512, 256, 0><<<dim3(8, 4, BATCH), 256, GEMM_SMEM>>>(
        w_attn, (const float*)afp, b_attn, out, 1.0f);
}

// round 6
// speedup vs baseline: 5.3552x; 1.0945x over previous
#include <cuda_runtime.h>
#include <cuda_fp16.h>
#include <cstdint>

#define BATCH 8
#define HW    1024
#define QKV_CH 768

// Scratch (device globals; no allocation allowed)
__device__ __half g_qkvh[BATCH * QKV_CH * HW];  // [b][768][1024] fp16
__device__ __half g_afh [BATCH * 256   * HW];   // attention out (scrambled layout) fp16

// ===========================================================================
// helpers
// ===========================================================================
__device__ __forceinline__ uint32_t smem_u32(const void* p) {
    uint32_t a;
    asm("{ .reg .u64 t; cvta.to.shared.u64 t, %1; cvt.u32.u64 %0, t; }"
        : "=r"(a) : "l"(p));
    return a;
}
__device__ __forceinline__ void mma16816(float* c, const uint32_t* a, const uint32_t* b) {
    asm volatile("mma.sync.aligned.m16n8k16.row.col.f32.f16.f16.f32 "
        "{%0,%1,%2,%3}, {%4,%5,%6,%7}, {%8,%9}, {%0,%1,%2,%3};"
        : "+f"(c[0]), "+f"(c[1]), "+f"(c[2]), "+f"(c[3])
        : "r"(a[0]), "r"(a[1]), "r"(a[2]), "r"(a[3]), "r"(b[0]), "r"(b[1]));
}
__device__ __forceinline__ void ldsm_x4(uint32_t* r, uint32_t addr) {
    asm volatile("ldmatrix.sync.aligned.m8n8.x4.shared.b16 {%0,%1,%2,%3}, [%4];"
        : "=r"(r[0]), "=r"(r[1]), "=r"(r[2]), "=r"(r[3]) : "r"(addr));
}
__device__ __forceinline__ void ldsm_x4t(uint32_t* r, uint32_t addr) {
    asm volatile("ldmatrix.sync.aligned.m8n8.x4.trans.shared.b16 {%0,%1,%2,%3}, [%4];"
        : "=r"(r[0]), "=r"(r[1]), "=r"(r[2]), "=r"(r[3]) : "r"(addr));
}
__device__ __forceinline__ uint32_t pack_h2(float lo, float hi) {
    __half2 h = __floats2half2_rn(lo, hi);
    return *reinterpret_cast<uint32_t*>(&h);
}
__device__ __forceinline__ uint32_t hh2pack(__half a, __half b) {
    __half2 h = __halves2half2(a, b);
    return *reinterpret_cast<uint32_t*>(&h);
}
__device__ __forceinline__ float2 h2f2(uint32_t u) {
    __half2 h = *reinterpret_cast<__half2*>(&u);
    return __half22float2(h);
}
#define CP_ASYNC16(dst, src) \
    asm volatile("cp.async.cg.shared.global [%0], [%1], 16;" \
                 :: "r"(dst), "l"(src) : "memory")
#define CP_COMMIT() asm volatile("cp.async.commit_group;" ::: "memory")
#define CP_WAIT1()  asm volatile("cp.async.wait_group 1;" ::: "memory")

// packed fp32x2
typedef unsigned long long ull;
__device__ __forceinline__ ull fma2v(ull a, ull b, ull c) {
    ull d; asm("fma.rn.f32x2 %0, %1, %2, %3;" : "=l"(d) : "l"(a), "l"(b), "l"(c)); return d;
}
__device__ __forceinline__ ull mul2v(ull a, ull b) {
    ull d; asm("mul.rn.f32x2 %0, %1, %2;" : "=l"(d) : "l"(a), "l"(b)); return d;
}
__device__ __forceinline__ ull add2v(ull a, ull b) {
    ull d; asm("add.rn.f32x2 %0, %1, %2;" : "=l"(d) : "l"(a), "l"(b)); return d;
}
__device__ __forceinline__ ull dup2(float v) {
    ull r; uint32_t u = __float_as_uint(v);
    asm("mov.b64 %0, {%1, %1};" : "=l"(r) : "r"(u));
    return r;
}
__device__ __forceinline__ ull pk2(float x, float y) {
    ull r; uint32_t a = __float_as_uint(x), b = __float_as_uint(y);
    asm("mov.b64 %0, {%1, %2};" : "=l"(r) : "r"(a), "r"(b));
    return r;
}
__device__ __forceinline__ float frcp(float x) {
    float r = __int_as_float(0x7EF311C3 - __float_as_int(x));
    r = r * (2.0f - x * r);
    r = r * (2.0f - x * r);
    r = r * (2.0f - x * r);
    return r;
}
__device__ __forceinline__ void exp2pairf(ull l, float& elo, float& ehi) {
    const ull LOG2E2 = dup2(1.4426950408889634f);
    const ull MAGIC2 = dup2(12582912.0f);
    const ull NMAGIC2 = dup2(-12582912.0f);
    const ull NONE2  = dup2(-1.0f);
    ull y  = mul2v(l, LOG2E2);
    ull tt = add2v(y, MAGIC2);
    ull nn2 = add2v(tt, NMAGIC2);
    ull f  = fma2v(nn2, NONE2, y);
    ull pe = fma2v(dup2(9.6183290401232e-3f), f, dup2(5.550410866482158e-2f));
    pe = fma2v(pe, f, dup2(2.402265069591007e-1f));
    pe = fma2v(pe, f, dup2(6.931471805599453e-1f));
    pe = fma2v(pe, f, dup2(1.0f));
    uint32_t tlo, thi, plo, phi;
    asm("mov.b64 {%0,%1}, %2;" : "=r"(tlo), "=r"(thi) : "l"(tt));
    asm("mov.b64 {%0,%1}, %2;" : "=r"(plo), "=r"(phi) : "l"(pe));
    elo = __int_as_float((int)((tlo << 23) + plo));
    ehi = __int_as_float((int)((thi << 23) + phi));
}

// ===========================================================================
// fp16 mma.sync GEMM: Y[b][m][n] = sum_k W[m][k] * X[b][k][n] + bias[m]
// TX: float (cvt at staging) or __half (direct copy). TY: float or __half.
// CTA tile 128x128, BK=32, 8 warps (2m x 4n), m16n8k16, ldmatrix fragments.
// ===========================================================================
static constexpr int ASZ = 128 * 80;
static constexpr int BSZ = 32 * 272;
static constexpr int GEMM_SMEM = 2 * (ASZ + BSZ);

template<int M, int K, int SCALE_ROWS, typename TX, typename TY>
__global__ __launch_bounds__(256, 2)
void gemm_mma(const float* __restrict__ W, const TX* __restrict__ X,
              const float* __restrict__ bias, TY* __restrict__ Y,
              float scaleVal)
{
    extern __shared__ char smraw[];
    const uint32_t smb = smem_u32(smraw);

    const int t    = threadIdx.x;
    const int lane = t & 31;
    const int wid  = t >> 5;
    const int g    = lane >> 2;
    const int t4   = lane & 3;
    const int wm   = (wid & 1) * 64;
    const int wn   = (wid >> 1) * 32;
    const int b    = blockIdx.z;
    const int m0   = blockIdx.y * 128;
    const int n0   = blockIdx.x * 128;
    const TX* Xb = X + (size_t)b * K * 1024;
    TY*       Yb = Y + (size_t)b * M * 1024;

    const int r16 = lane & 15;
    const int c8  = (lane >> 4) * 8;
    const uint32_t aAddr = smb + (wm + r16) * 80 + c8 * 2;
    const uint32_t bAddr = smb + 2 * ASZ + r16 * 272 + (wn + c8) * 2;

    const int am = t >> 3;
    const int ak = (t & 7) * 4;
    const int bk = t >> 5;
    const int bn = (t & 31) * 4;

    float4 aw[4];
    float4 bwf[4];
    uint2  bwh[4];
    float acc[4][4][4];
#pragma unroll
    for (int i = 0; i < 4; i++)
#pragma unroll
        for (int j = 0; j < 4; j++)
#pragma unroll
            for (int q = 0; q < 4; q++) acc[i][j][q] = 0.f;

    auto LOADR = [&](int kc) {
#pragma unroll
        for (int c = 0; c < 4; c++)
            aw[c] = *(const float4*)&W[(size_t)(m0 + am + c * 32) * K + kc * 32 + ak];
#pragma unroll
        for (int c = 0; c < 4; c++) {
            if constexpr (sizeof(TX) == 2)
                bwh[c] = *(const uint2*)&Xb[(size_t)(kc * 32 + bk + c * 8) * 1024 + n0 + bn];
            else
                bwf[c] = *(const float4*)&Xb[(size_t)(kc * 32 + bk + c * 8) * 1024 + n0 + bn];
        }
    };
    auto STORE = [&](int st) {
        char* A  = smraw + st * ASZ;
        char* Bm = smraw + 2 * ASZ + st * BSZ;
#pragma unroll
        for (int c = 0; c < 4; c++) {
            uint2 v;
            v.x = pack_h2(aw[c].x, aw[c].y);
            v.y = pack_h2(aw[c].z, aw[c].w);
            *(uint2*)(A + (am + c * 32) * 80 + ak * 2) = v;
        }
#pragma unroll
        for (int c = 0; c < 4; c++) {
            if constexpr (sizeof(TX) == 2) {
                *(uint2*)(Bm + (bk + c * 8) * 272 + bn * 2) = bwh[c];
            } else {
                uint2 v;
                v.x = pack_h2(bwf[c].x, bwf[c].y);
                v.y = pack_h2(bwf[c].z, bwf[c].w);
                *(uint2*)(Bm + (bk + c * 8) * 272 + bn * 2) = v;
            }
        }
    };

    const int NC = K / 32;
    LOADR(0);
    STORE(0);
    __syncthreads();

    for (int kc = 0; kc < NC; kc++) {
        if (kc + 1 < NC) LOADR(kc + 1);

        const uint32_t aB = aAddr + (kc & 1) * ASZ;
        const uint32_t bB = bAddr + (kc & 1) * BSZ;
#pragma unroll
        for (int s = 0; s < 2; s++) {
            uint32_t afr[4][4], bfr[2][4];
#pragma unroll
            for (int mf = 0; mf < 4; mf++)
                ldsm_x4(afr[mf], aB + mf * 16 * 80 + s * 32);
#pragma unroll
            for (int np = 0; np < 2; np++)
                ldsm_x4t(bfr[np], bB + np * 32 + s * 16 * 272);
#pragma unroll
            for (int mf = 0; mf < 4; mf++)
#pragma unroll
                for (int np = 0; np < 2; np++) {
                    mma16816(acc[mf][2 * np],     afr[mf], bfr[np] + 0);
                    mma16816(acc[mf][2 * np + 1], afr[mf], bfr[np] + 2);
                }
        }
        if (kc + 1 < NC) STORE((kc + 1) & 1);
        __syncthreads();
    }

    // epilogue: bias (+ optional q scale)
#pragma unroll
    for (int mf = 0; mf < 4; mf++) {
        int r0 = m0 + wm + mf * 16 + g;
        int r1 = r0 + 8;
        float b0v = bias[r0], b1v = bias[r1];
        float s0 = (SCALE_ROWS > 0 && r0 < SCALE_ROWS) ? scaleVal : 1.f;
        float s1 = (SCALE_ROWS > 0 && r1 < SCALE_ROWS) ? scaleVal : 1.f;
#pragma unroll
        for (int nf = 0; nf < 4; nf++) {
            int nc = n0 + wn + nf * 8 + 2 * t4;
            if constexpr (sizeof(TY) == 2) {
                *(uint32_t*)&Yb[(size_t)r0 * 1024 + nc] =
                    pack_h2((acc[mf][nf][0] + b0v) * s0, (acc[mf][nf][1] + b0v) * s0);
                *(uint32_t*)&Yb[(size_t)r1 * 1024 + nc] =
                    pack_h2((acc[mf][nf][2] + b1v) * s1, (acc[mf][nf][3] + b1v) * s1);
            } else {
                float2 v0, v1;
                v0.x = (acc[mf][nf][0] + b0v) * s0;
                v0.y = (acc[mf][nf][1] + b0v) * s0;
                v1.x = (acc[mf][nf][2] + b1v) * s1;
                v1.y = (acc[mf][nf][3] + b1v) * s1;
                *(float2*)&Yb[(size_t)r0 * 1024 + nc] = v0;
                *(float2*)&Yb[(size_t)r1 * 1024 + nc] = v1;
            }
        }
    }
}

// ===========================================================================
// fp16 tensor-core fused attention, cp.async double-buffered K/V staging.
// Block = (b, 32-q tile); warp = head. Softmax across the 8 HEADS.
// Output in the reference's scrambled flat-reshape layout (fp16).
// ===========================================================================
static constexpr int KS_OFF = 0;        // 2 x 20480 (double buffer)
static constexpr int VS_OFF = 40960;    // 2 x 20480
static constexpr int ES_OFF = 81920;    // 20480
static constexpr int ATTN_SMEM = 102400;

__global__ __launch_bounds__(256, 2)
void attn_mma(const __half* __restrict__ qkvh, __half* __restrict__ af)
{
    extern __shared__ char smraw[];
    const uint32_t smb = smem_u32(smraw);
    __half* EsH = (__half*)(smraw + ES_OFF);

    const int b    = blockIdx.y;
    const int qt   = blockIdx.x;
    const int q0   = qt * 32;
    const int t    = threadIdx.x;
    const int lane = t & 31;
    const int n    = t >> 5;              // warp = head
    const int g    = lane >> 2;
    const int t4   = lane & 3;

    const int r16 = lane & 15;
    const int c8  = (lane >> 4) * 8;
    const int r2  = (lane & 7) + (lane >> 4) * 8;
    const int c2  = ((lane >> 3) & 1) * 8;

    const __half* qbh = qkvh + (size_t)b * QKV_CH * HW;

    // ---- preload Q A-fragments (fp16 source) ----
    uint32_t qa[2][2][4];
    {
        const int qg = q0 + g;
#pragma unroll
        for (int mf = 0; mf < 2; mf++)
#pragma unroll
            for (int s = 0; s < 2; s++) {
                int d0 = s * 16 + 2 * t4;
                const __half* ra = qbh + (size_t)(n * 32 + d0) * HW;
                const __half* rb = qbh + (size_t)(n * 32 + d0 + 1) * HW;
                const __half* rc = qbh + (size_t)(n * 32 + d0 + 8) * HW;
                const __half* rd = qbh + (size_t)(n * 32 + d0 + 9) * HW;
                int qq = qg + mf * 16;
                qa[mf][s][0] = hh2pack(ra[qq],     rb[qq]);
                qa[mf][s][1] = hh2pack(ra[qq + 8], rb[qq + 8]);
                qa[mf][s][2] = hh2pack(rc[qq],     rd[qq]);
                qa[mf][s][3] = hh2pack(rc[qq + 8], rd[qq + 8]);
            }
    }

    float oacc[2][4][4];
#pragma unroll
    for (int i = 0; i < 2; i++)
#pragma unroll
        for (int j = 0; j < 4; j++)
#pragma unroll
            for (int q = 0; q < 4; q++) oacc[i][j][q] = 0.f;

    const uint32_t sbK = smb + KS_OFF + ((n * 32 + r16) * 40 + c8) * 2;
    const uint32_t sbV = smb + VS_OFF + ((n * 32 + r16) * 40 + c8) * 2;
    const uint32_t sbE = smb + ES_OFF + ((n * 32 + r2) * 40 + c2) * 2;

    // cp.async prefetch of one 32-wide k-tile (K + V) into buffer (kt&1)
    auto PREFETCH = [&](int kt2) {
        const int k0  = (kt2 & 31) * 32;
        const int bo  = (kt2 & 1) * 20480;
#pragma unroll
        for (int c = 0; c < 4; c++) {
            int idx = c * 256 + t;
            int row = idx >> 2;
            int col = (idx & 3) * 8;
            uint32_t dK = smb + KS_OFF + bo + row * 80 + col * 2;
            CP_ASYNC16(dK, qbh + (size_t)(256 + row) * HW + k0 + col);
            uint32_t dV = smb + VS_OFF + bo + row * 80 + col * 2;
            CP_ASYNC16(dV, qbh + (size_t)(512 + row) * HW + k0 + col);
        }
        CP_COMMIT();
    };

    PREFETCH(0);

    for (int kt = 0; kt < 32; kt++) {
        __syncthreads();           // all warps done reading buf[(kt+1)&1] (iter kt-1)
        PREFETCH(kt + 1);          // overlaps with this iteration's compute
        CP_WAIT1();                // group kt landed (this thread)
        __syncthreads();           // ... and all threads'

        const uint32_t bo = (kt & 1) * 20480;

        // ---- S = Q^T K -> exp -> Es (fp16) ----
        __half* EsN = EsH + n * 32 * 40;
#pragma unroll
        for (int np = 0; np < 2; np++) {
            float sacc[2][2][4];
#pragma unroll
            for (int mf = 0; mf < 2; mf++)
#pragma unroll
                for (int nn = 0; nn < 2; nn++)
#pragma unroll
                    for (int q = 0; q < 4; q++) sacc[mf][nn][q] = 0.f;
#pragma unroll
            for (int s = 0; s < 2; s++) {
                uint32_t bk[4];
                ldsm_x4t(bk, sbK + bo + s * 16 * 80 + np * 32);
#pragma unroll
                for (int mf = 0; mf < 2; mf++) {
                    mma16816(sacc[mf][0], qa[mf][s], bk + 0);
                    mma16816(sacc[mf][1], qa[mf][s], bk + 2);
                }
            }
#pragma unroll
            for (int mf = 0; mf < 2; mf++)
#pragma unroll
                for (int nn = 0; nn < 2; nn++) {
                    int kp = (np * 2 + nn) * 8 + 2 * t4;
                    int qr = mf * 16 + g;
                    float e0, e1, e2, e3;
                    exp2pairf(pk2(sacc[mf][nn][0], sacc[mf][nn][1]), e0, e1);
                    exp2pairf(pk2(sacc[mf][nn][2], sacc[mf][nn][3]), e2, e3);
                    *(uint32_t*)(EsN + qr * 40 + kp)       = pack_h2(e0, e1);
                    *(uint32_t*)(EsN + (qr + 8) * 40 + kp) = pack_h2(e2, e3);
                }
        }
        __syncthreads();

        // ---- cross-head denominators + Newton recip + rescale (fp16) ----
#pragma unroll
        for (int j = 0; j < 2; j++) {
            int P  = (t << 1) | j;
            int qr = P >> 4;
            int kp = (P & 15) << 1;
            __half* base = EsH + qr * 40 + kp;
            uint32_t ev[8];
            float sx = 0.f, sy = 0.f;
#pragma unroll
            for (int n2 = 0; n2 < 8; n2++) {
                ev[n2] = *(uint32_t*)(base + n2 * (32 * 40));
                float2 f = h2f2(ev[n2]);
                sx += f.x; sy += f.y;
            }
            float rx = frcp(sx), ry = frcp(sy);
#pragma unroll
            for (int n2 = 0; n2 < 8; n2++) {
                float2 f = h2f2(ev[n2]);
                *(uint32_t*)(base + n2 * (32 * 40)) = pack_h2(f.x * rx, f.y * ry);
            }
        }
        __syncthreads();

        // ---- O += V W ----
#pragma unroll
        for (int ks = 0; ks < 2; ks++) {
            uint32_t va[2][4], wb[2][4];
            ldsm_x4(va[0], sbV + bo + ks * 32);
            ldsm_x4(va[1], sbV + bo + 16 * 80 + ks * 32);
            ldsm_x4(wb[0], sbE + ks * 32);
            ldsm_x4(wb[1], sbE + 16 * 80 + ks * 32);
#pragma unroll
            for (int mf = 0; mf < 2; mf++)
#pragma unroll
                for (int np = 0; np < 2; np++) {
                    mma16816(oacc[mf][2 * np],     va[mf], wb[np] + 0);
                    mma16816(oacc[mf][2 * np + 1], va[mf], wb[np] + 2);
                }
        }
    }

    // ---- epilogue: scrambled flat-reshape layout, fp16 ----
    __half* ob = af + ((size_t)(b * 256 + n * 32 + qt)) * 1024;
#pragma unroll
    for (int mf = 0; mf < 2; mf++)
#pragma unroll
        for (int nf = 0; nf < 4; nf++) {
            int d = 16 * mf + g;
            int q = 8 * nf + 2 * t4;
            ob[q * 32 + d]           = __float2half_rn(oacc[mf][nf][0]);
            ob[(q + 1) * 32 + d]     = __float2half_rn(oacc[mf][nf][1]);
            ob[q * 32 + d + 8]       = __float2half_rn(oacc[mf][nf][2]);
            ob[(q + 1) * 32 + d + 8] = __float2half_rn(oacc[mf][nf][3]);
        }
}

// ---------------------------------------------------------------------------
extern "C" void kernel_launch(void* const* d_in, const int* in_sizes, int n_in,
                              void* d_out, int out_size)
{
    const float* x      = (const float*)d_in[0];   // [8,512,32,32]
    const float* w_qkv  = (const float*)d_in[1];   // [768,512]
    const float* b_qkv  = (const float*)d_in[2];   // [768]
    const float* w_attn = (const float*)d_in[3];   // [512,256]
    const float* b_attn = (const float*)d_in[4];   // [512]
    float* out = (float*)d_out;                    // [8,512,32,32]

    void* qkvp = nullptr;
    void* afp  = nullptr;
    cudaGetSymbolAddress(&qkvp, g_qkvh);
    cudaGetSymbolAddress(&afp,  g_afh);

    cudaFuncSetAttribute((const void*)gemm_mma<768, 512, 256, float, __half>,
                         cudaFuncAttributeMaxDynamicSharedMemorySize, GEMM_SMEM);
    cudaFuncSetAttribute((const void*)gemm_mma<512, 256, 0, __half, float>,
                         cudaFuncAttributeMaxDynamicSharedMemorySize, GEMM_SMEM);
    cudaFuncSetAttribute((const void*)attn_mma,
                         cudaFuncAttributeMaxDynamicSharedMemorySize, ATTN_SMEM);

    // 1) QKV projection (fp16 mma; bias; q rows scaled; fp16 output)
    gemm_mma<768, 512, 256, float, __half><<<dim3(8, 6, BATCH), 256, GEMM_SMEM>>>(
        w_qkv, x, b_qkv, (__half*)qkvp, 0.17677669529663687f);

    // 2) fp16 fused attention (head-softmax), cp.async double-buffered
    attn_mma<<<dim3(32, BATCH), 256, ATTN_SMEM>>>((const __half*)qkvp,
                                                  (__half*)afp);

    // 3) output projection (fp16 mma; fp16 input; fp32 output)
    gemm_mma<512, 256, 0, __half, float><<<dim3(8, 4, BATCH), 256, GEMM_SMEM>>>(
        w_attn, (const __half*)afp, b_attn, out, 1.0f);
}

// round 7
// speedup vs baseline: 5.4849x; 1.0242x over previous
#include <cuda_runtime.h>
#include <cuda_fp16.h>
#include <cstdint>

#define BATCH 8
#define HW    1024
#define QKV_CH 768

// Scratch (device globals; no allocation allowed)
__device__ __half g_qkvh[BATCH * QKV_CH * HW];  // [b][768][1024] fp16
__device__ __half g_afh [BATCH * 256   * HW];   // attention out (scrambled layout) fp16

// ===========================================================================
// helpers
// ===========================================================================
__device__ __forceinline__ uint32_t smem_u32(const void* p) {
    uint32_t a;
    asm("{ .reg .u64 t; cvta.to.shared.u64 t, %1; cvt.u32.u64 %0, t; }"
        : "=r"(a) : "l"(p));
    return a;
}
__device__ __forceinline__ void mma16816(float* c, const uint32_t* a, const uint32_t* b) {
    asm volatile("mma.sync.aligned.m16n8k16.row.col.f32.f16.f16.f32 "
        "{%0,%1,%2,%3}, {%4,%5,%6,%7}, {%8,%9}, {%0,%1,%2,%3};"
        : "+f"(c[0]), "+f"(c[1]), "+f"(c[2]), "+f"(c[3])
        : "r"(a[0]), "r"(a[1]), "r"(a[2]), "r"(a[3]), "r"(b[0]), "r"(b[1]));
}
__device__ __forceinline__ void ldsm_x4(uint32_t* r, uint32_t addr) {
    asm volatile("ldmatrix.sync.aligned.m8n8.x4.shared.b16 {%0,%1,%2,%3}, [%4];"
        : "=r"(r[0]), "=r"(r[1]), "=r"(r[2]), "=r"(r[3]) : "r"(addr));
}
__device__ __forceinline__ void ldsm_x4t(uint32_t* r, uint32_t addr) {
    asm volatile("ldmatrix.sync.aligned.m8n8.x4.trans.shared.b16 {%0,%1,%2,%3}, [%4];"
        : "=r"(r[0]), "=r"(r[1]), "=r"(r[2]), "=r"(r[3]) : "r"(addr));
}
__device__ __forceinline__ uint32_t pack_h2(float lo, float hi) {
    __half2 h = __floats2half2_rn(lo, hi);
    return *reinterpret_cast<uint32_t*>(&h);
}
__device__ __forceinline__ uint32_t hh2pack(__half a, __half b) {
    __half2 h = __halves2half2(a, b);
    return *reinterpret_cast<uint32_t*>(&h);
}
__device__ __forceinline__ float2 h2f2(uint32_t u) {
    __half2 h = *reinterpret_cast<__half2*>(&u);
    return __half22float2(h);
}
#define CP_ASYNC16(dst, src) \
    asm volatile("cp.async.cg.shared.global [%0], [%1], 16;" \
                 :: "r"(dst), "l"(src) : "memory")
#define CP_COMMIT() asm volatile("cp.async.commit_group;" ::: "memory")
#define CP_WAIT1()  asm volatile("cp.async.wait_group 1;" ::: "memory")

// packed fp32x2
typedef unsigned long long ull;
__device__ __forceinline__ ull fma2v(ull a, ull b, ull c) {
    ull d; asm("fma.rn.f32x2 %0, %1, %2, %3;" : "=l"(d) : "l"(a), "l"(b), "l"(c)); return d;
}
__device__ __forceinline__ ull mul2v(ull a, ull b) {
    ull d; asm("mul.rn.f32x2 %0, %1, %2;" : "=l"(d) : "l"(a), "l"(b)); return d;
}
__device__ __forceinline__ ull add2v(ull a, ull b) {
    ull d; asm("add.rn.f32x2 %0, %1, %2;" : "=l"(d) : "l"(a), "l"(b)); return d;
}
__device__ __forceinline__ ull dup2(float v) {
    ull r; uint32_t u = __float_as_uint(v);
    asm("mov.b64 %0, {%1, %1};" : "=l"(r) : "r"(u));
    return r;
}
__device__ __forceinline__ ull pk2(float x, float y) {
    ull r; uint32_t a = __float_as_uint(x), b = __float_as_uint(y);
    asm("mov.b64 %0, {%1, %2};" : "=l"(r) : "r"(a), "r"(b));
    return r;
}
__device__ __forceinline__ float frcp(float x) {
    float r = __int_as_float(0x7EF311C3 - __float_as_int(x));
    r = r * (2.0f - x * r);
    r = r * (2.0f - x * r);
    r = r * (2.0f - x * r);
    return r;
}
__device__ __forceinline__ void exp2pairf(ull l, float& elo, float& ehi) {
    const ull LOG2E2 = dup2(1.4426950408889634f);
    const ull MAGIC2 = dup2(12582912.0f);
    const ull NMAGIC2 = dup2(-12582912.0f);
    const ull NONE2  = dup2(-1.0f);
    ull y  = mul2v(l, LOG2E2);
    ull tt = add2v(y, MAGIC2);
    ull nn2 = add2v(tt, NMAGIC2);
    ull f  = fma2v(nn2, NONE2, y);
    ull pe = fma2v(dup2(9.6183290401232e-3f), f, dup2(5.550410866482158e-2f));
    pe = fma2v(pe, f, dup2(2.402265069591007e-1f));
    pe = fma2v(pe, f, dup2(6.931471805599453e-1f));
    pe = fma2v(pe, f, dup2(1.0f));
    uint32_t tlo, thi, plo, phi;
    asm("mov.b64 {%0,%1}, %2;" : "=r"(tlo), "=r"(thi) : "l"(tt));
    asm("mov.b64 {%0,%1}, %2;" : "=r"(plo), "=r"(phi) : "l"(pe));
    elo = __int_as_float((int)((tlo << 23) + plo));
    ehi = __int_as_float((int)((thi << 23) + phi));
}

// ===========================================================================
// fp16 mma.sync GEMM (unchanged from round 6)
// ===========================================================================
static constexpr int ASZ = 128 * 80;
static constexpr int BSZ = 32 * 272;
static constexpr int GEMM_SMEM = 2 * (ASZ + BSZ);

template<int M, int K, int SCALE_ROWS, typename TX, typename TY>
__global__ __launch_bounds__(256, 2)
void gemm_mma(const float* __restrict__ W, const TX* __restrict__ X,
              const float* __restrict__ bias, TY* __restrict__ Y,
              float scaleVal)
{
    extern __shared__ char smraw[];
    const uint32_t smb = smem_u32(smraw);

    const int t    = threadIdx.x;
    const int lane = t & 31;
    const int wid  = t >> 5;
    const int g    = lane >> 2;
    const int t4   = lane & 3;
    const int wm   = (wid & 1) * 64;
    const int wn   = (wid >> 1) * 32;
    const int b    = blockIdx.z;
    const int m0   = blockIdx.y * 128;
    const int n0   = blockIdx.x * 128;
    const TX* Xb = X + (size_t)b * K * 1024;
    TY*       Yb = Y + (size_t)b * M * 1024;

    const int r16 = lane & 15;
    const int c8  = (lane >> 4) * 8;
    const uint32_t aAddr = smb + (wm + r16) * 80 + c8 * 2;
    const uint32_t bAddr = smb + 2 * ASZ + r16 * 272 + (wn + c8) * 2;

    const int am = t >> 3;
    const int ak = (t & 7) * 4;
    const int bk = t >> 5;
    const int bn = (t & 31) * 4;

    float4 aw[4];
    float4 bwf[4];
    uint2  bwh[4];
    float acc[4][4][4];
#pragma unroll
    for (int i = 0; i < 4; i++)
#pragma unroll
        for (int j = 0; j < 4; j++)
#pragma unroll
            for (int q = 0; q < 4; q++) acc[i][j][q] = 0.f;

    auto LOADR = [&](int kc) {
#pragma unroll
        for (int c = 0; c < 4; c++)
            aw[c] = *(const float4*)&W[(size_t)(m0 + am + c * 32) * K + kc * 32 + ak];
#pragma unroll
        for (int c = 0; c < 4; c++) {
            if constexpr (sizeof(TX) == 2)
                bwh[c] = *(const uint2*)&Xb[(size_t)(kc * 32 + bk + c * 8) * 1024 + n0 + bn];
            else
                bwf[c] = *(const float4*)&Xb[(size_t)(kc * 32 + bk + c * 8) * 1024 + n0 + bn];
        }
    };
    auto STORE = [&](int st) {
        char* A  = smraw + st * ASZ;
        char* Bm = smraw + 2 * ASZ + st * BSZ;
#pragma unroll
        for (int c = 0; c < 4; c++) {
            uint2 v;
            v.x = pack_h2(aw[c].x, aw[c].y);
            v.y = pack_h2(aw[c].z, aw[c].w);
            *(uint2*)(A + (am + c * 32) * 80 + ak * 2) = v;
        }
#pragma unroll
        for (int c = 0; c < 4; c++) {
            if constexpr (sizeof(TX) == 2) {
                *(uint2*)(Bm + (bk + c * 8) * 272 + bn * 2) = bwh[c];
            } else {
                uint2 v;
                v.x = pack_h2(bwf[c].x, bwf[c].y);
                v.y = pack_h2(bwf[c].z, bwf[c].w);
                *(uint2*)(Bm + (bk + c * 8) * 272 + bn * 2) = v;
            }
        }
    };

    const int NC = K / 32;
    LOADR(0);
    STORE(0);
    __syncthreads();

    for (int kc = 0; kc < NC; kc++) {
        if (kc + 1 < NC) LOADR(kc + 1);

        const uint32_t aB = aAddr + (kc & 1) * ASZ;
        const uint32_t bB = bAddr + (kc & 1) * BSZ;
#pragma unroll
        for (int s = 0; s < 2; s++) {
            uint32_t afr[4][4], bfr[2][4];
#pragma unroll
            for (int mf = 0; mf < 4; mf++)
                ldsm_x4(afr[mf], aB + mf * 16 * 80 + s * 32);
#pragma unroll
            for (int np = 0; np < 2; np++)
                ldsm_x4t(bfr[np], bB + np * 32 + s * 16 * 272);
#pragma unroll
            for (int mf = 0; mf < 4; mf++)
#pragma unroll
                for (int np = 0; np < 2; np++) {
                    mma16816(acc[mf][2 * np],     afr[mf], bfr[np] + 0);
                    mma16816(acc[mf][2 * np + 1], afr[mf], bfr[np] + 2);
                }
        }
        if (kc + 1 < NC) STORE((kc + 1) & 1);
        __syncthreads();
    }

#pragma unroll
    for (int mf = 0; mf < 4; mf++) {
        int r0 = m0 + wm + mf * 16 + g;
        int r1 = r0 + 8;
        float b0v = bias[r0], b1v = bias[r1];
        float s0 = (SCALE_ROWS > 0 && r0 < SCALE_ROWS) ? scaleVal : 1.f;
        float s1 = (SCALE_ROWS > 0 && r1 < SCALE_ROWS) ? scaleVal : 1.f;
#pragma unroll
        for (int nf = 0; nf < 4; nf++) {
            int nc = n0 + wn + nf * 8 + 2 * t4;
            if constexpr (sizeof(TY) == 2) {
                *(uint32_t*)&Yb[(size_t)r0 * 1024 + nc] =
                    pack_h2((acc[mf][nf][0] + b0v) * s0, (acc[mf][nf][1] + b0v) * s0);
                *(uint32_t*)&Yb[(size_t)r1 * 1024 + nc] =
                    pack_h2((acc[mf][nf][2] + b1v) * s1, (acc[mf][nf][3] + b1v) * s1);
            } else {
                float2 v0, v1;
                v0.x = (acc[mf][nf][0] + b0v) * s0;
                v0.y = (acc[mf][nf][1] + b0v) * s0;
                v1.x = (acc[mf][nf][2] + b1v) * s1;
                v1.y = (acc[mf][nf][3] + b1v) * s1;
                *(float2*)&Yb[(size_t)r0 * 1024 + nc] = v0;
                *(float2*)&Yb[(size_t)r1 * 1024 + nc] = v1;
            }
        }
    }
}

// ===========================================================================
// fp16 tensor-core fused attention, q-tile 64, 512 threads.
// Warp w = (qhalf = w>>3, head = w&7); each warp does a 32-q subtile of its
// head — identical per-warp work to round 6, but K/V staging, barriers, and
// blocks are amortized over 64 queries. Softmax across the 8 HEADS.
// Output in the reference's scrambled flat-reshape layout (fp16).
// ===========================================================================
static constexpr int KS_OFF = 0;        // 2 x 20480 (double buffer)
static constexpr int VS_OFF = 40960;    // 2 x 20480
static constexpr int ES_OFF = 81920;    // [2 qh][8 n][32 q][40] = 40960
static constexpr int ATTN_SMEM = 122880;

__global__ __launch_bounds__(512, 1)
void attn_mma(const __half* __restrict__ qkvh, __half* __restrict__ af)
{
    extern __shared__ char smraw[];
    const uint32_t smb = smem_u32(smraw);
    __half* EsH = (__half*)(smraw + ES_OFF);

    const int b    = blockIdx.y;
    const int qt   = blockIdx.x;           // 16 tiles of 64 queries
    const int q0   = qt * 64;
    const int t    = threadIdx.x;
    const int lane = t & 31;
    const int w    = t >> 5;               // 16 warps
    const int n    = w & 7;                // head
    const int qh   = w >> 3;               // q-half (0/1)
    const int g    = lane >> 2;
    const int t4   = lane & 3;

    const int r16 = lane & 15;
    const int c8  = (lane >> 4) * 8;
    const int r2  = (lane & 7) + (lane >> 4) * 8;
    const int c2  = ((lane >> 3) & 1) * 8;

    const __half* qbh = qkvh + (size_t)b * QKV_CH * HW;

    // ---- preload Q A-fragments for this warp's 32-q subtile ----
    uint32_t qa[2][2][4];
    {
        const int qg = q0 + qh * 32 + g;
#pragma unroll
        for (int mf = 0; mf < 2; mf++)
#pragma unroll
            for (int s = 0; s < 2; s++) {
                int d0 = s * 16 + 2 * t4;
                const __half* ra = qbh + (size_t)(n * 32 + d0) * HW;
                const __half* rb = qbh + (size_t)(n * 32 + d0 + 1) * HW;
                const __half* rc = qbh + (size_t)(n * 32 + d0 + 8) * HW;
                const __half* rd = qbh + (size_t)(n * 32 + d0 + 9) * HW;
                int qq = qg + mf * 16;
                qa[mf][s][0] = hh2pack(ra[qq],     rb[qq]);
                qa[mf][s][1] = hh2pack(ra[qq + 8], rb[qq + 8]);
                qa[mf][s][2] = hh2pack(rc[qq],     rd[qq]);
                qa[mf][s][3] = hh2pack(rc[qq + 8], rd[qq + 8]);
            }
    }

    float oacc[2][4][4];
#pragma unroll
    for (int i = 0; i < 2; i++)
#pragma unroll
        for (int j = 0; j < 4; j++)
#pragma unroll
            for (int q = 0; q < 4; q++) oacc[i][j][q] = 0.f;

    const uint32_t sbK = smb + KS_OFF + ((n * 32 + r16) * 40 + c8) * 2;
    const uint32_t sbV = smb + VS_OFF + ((n * 32 + r16) * 40 + c8) * 2;
    const uint32_t sbE = smb + ES_OFF + (((qh * 8 + n) * 32 + r2) * 40 + c2) * 2;

    // cp.async prefetch of one 32-wide k-tile (K + V) into buffer (kt&1)
    auto PREFETCH = [&](int kt2) {
        const int k0 = (kt2 & 31) * 32;
        const int bo = (kt2 & 1) * 20480;
#pragma unroll
        for (int c = 0; c < 2; c++) {
            int idx = c * 512 + t;
            int row = idx >> 2;
            int col = (idx & 3) * 8;
            CP_ASYNC16(smb + KS_OFF + bo + row * 80 + col * 2,
                       qbh + (size_t)(256 + row) * HW + k0 + col);
            CP_ASYNC16(smb + VS_OFF + bo + row * 80 + col * 2,
                       qbh + (size_t)(512 + row) * HW + k0 + col);
        }
        CP_COMMIT();
    };

    PREFETCH(0);

    for (int kt = 0; kt < 32; kt++) {
        __syncthreads();           // all warps done reading buf[(kt+1)&1]
        PREFETCH(kt + 1);          // overlaps with this iteration's compute
        CP_WAIT1();                // group kt landed (this thread)
        __syncthreads();           // ... and all threads'

        const uint32_t bo = (kt & 1) * 20480;

        // ---- S = Q^T K -> exp -> Es (fp16) ----
        __half* EsN = EsH + (qh * 8 + n) * 32 * 40;
#pragma unroll
        for (int np = 0; np < 2; np++) {
            float sacc[2][2][4];
#pragma unroll
            for (int mf = 0; mf < 2; mf++)
#pragma unroll
                for (int nn = 0; nn < 2; nn++)
#pragma unroll
                    for (int q = 0; q < 4; q++) sacc[mf][nn][q] = 0.f;
#pragma unroll
            for (int s = 0; s < 2; s++) {
                uint32_t bk[4];
                ldsm_x4t(bk, sbK + bo + s * 16 * 80 + np * 32);
#pragma unroll
                for (int mf = 0; mf < 2; mf++) {
                    mma16816(sacc[mf][0], qa[mf][s], bk + 0);
                    mma16816(sacc[mf][1], qa[mf][s], bk + 2);
                }
            }
#pragma unroll
            for (int mf = 0; mf < 2; mf++)
#pragma unroll
                for (int nn = 0; nn < 2; nn++) {
                    int kp = (np * 2 + nn) * 8 + 2 * t4;
                    int qr = mf * 16 + g;
                    float e0, e1, e2, e3;
                    exp2pairf(pk2(sacc[mf][nn][0], sacc[mf][nn][1]), e0, e1);
                    exp2pairf(pk2(sacc[mf][nn][2], sacc[mf][nn][3]), e2, e3);
                    *(uint32_t*)(EsN + qr * 40 + kp)       = pack_h2(e0, e1);
                    *(uint32_t*)(EsN + (qr + 8) * 40 + kp) = pack_h2(e2, e3);
                }
        }
        __syncthreads();

        // ---- cross-head denominators + Newton recip + rescale (fp16) ----
        // 1024 (qh, q, kpos-pair) slots over 512 threads, 2 each.
#pragma unroll
        for (int j = 0; j < 2; j++) {
            int P   = (t << 1) | j;
            int qh2 = P >> 9;
            int qr  = (P >> 4) & 31;
            int kp  = (P & 15) << 1;
            __half* base = EsH + ((qh2 * 8) * 32 + qr) * 40 + kp;
            uint32_t ev[8];
            float sx = 0.f, sy = 0.f;
#pragma unroll
            for (int n2 = 0; n2 < 8; n2++) {
                ev[n2] = *(uint32_t*)(base + n2 * (32 * 40));
                float2 f = h2f2(ev[n2]);
                sx += f.x; sy += f.y;
            }
            float rx = frcp(sx), ry = frcp(sy);
#pragma unroll
            for (int n2 = 0; n2 < 8; n2++) {
                float2 f = h2f2(ev[n2]);
                *(uint32_t*)(base + n2 * (32 * 40)) = pack_h2(f.x * rx, f.y * ry);
            }
        }
        __syncthreads();

        // ---- O += V W ----
#pragma unroll
        for (int ks = 0; ks < 2; ks++) {
            uint32_t va[2][4], wb[2][4];
            ldsm_x4(va[0], sbV + bo + ks * 32);
            ldsm_x4(va[1], sbV + bo + 16 * 80 + ks * 32);
            ldsm_x4(wb[0], sbE + ks * 32);
            ldsm_x4(wb[1], sbE + 16 * 80 + ks * 32);
#pragma unroll
            for (int mf = 0; mf < 2; mf++)
#pragma unroll
                for (int np = 0; np < 2; np++) {
                    mma16816(oacc[mf][2 * np],     va[mf], wb[np] + 0);
                    mma16816(oacc[mf][2 * np + 1], va[mf], wb[np] + 2);
                }
        }
    }

    // ---- epilogue: scrambled flat-reshape layout, fp16 ----
    // AF row = b*256 + n*32 + (q>>5) = b*256 + n*32 + qt*2 + qh
    __half* ob = af + ((size_t)(b * 256 + n * 32 + qt * 2 + qh)) * 1024;
#pragma unroll
    for (int mf = 0; mf < 2; mf++)
#pragma unroll
        for (int nf = 0; nf < 4; nf++) {
            int d = 16 * mf + g;
            int q = 8 * nf + 2 * t4;
            ob[q * 32 + d]           = __float2half_rn(oacc[mf][nf][0]);
            ob[(q + 1) * 32 + d]     = __float2half_rn(oacc[mf][nf][1]);
            ob[q * 32 + d + 8]       = __float2half_rn(oacc[mf][nf][2]);
            ob[(q + 1) * 32 + d + 8] = __float2half_rn(oacc[mf][nf][3]);
        }
}

// ---------------------------------------------------------------------------
extern "C" void kernel_launch(void* const* d_in, const int* in_sizes, int n_in,
                              void* d_out, int out_size)
{
    const float* x      = (const float*)d_in[0];   // [8,512,32,32]
    const float* w_qkv  = (const float*)d_in[1];   // [768,512]
    const float* b_qkv  = (const float*)d_in[2];   // [768]
    const float* w_attn = (const float*)d_in[3];   // [512,256]
    const float* b_attn = (const float*)d_in[4];   // [512]
    float* out = (float*)d_out;                    // [8,512,32,32]

    void* qkvp = nullptr;
    void* afp  = nullptr;
    cudaGetSymbolAddress(&qkvp, g_qkvh);
    cudaGetSymbolAddress(&afp,  g_afh);

    cudaFuncSetAttribute((const void*)gemm_mma<768, 512, 256, float, __half>,
                         cudaFuncAttributeMaxDynamicSharedMemorySize, GEMM_SMEM);
    cudaFuncSetAttribute((const void*)gemm_mma<512, 256, 0, __half, float>,
                         cudaFuncAttributeMaxDynamicSharedMemorySize, GEMM_SMEM);
    cudaFuncSetAttribute((const void*)attn_mma,
                         cudaFuncAttributeMaxDynamicSharedMemorySize, ATTN_SMEM);

    // 1) QKV projection (fp16 mma; bias; q rows scaled; fp16 output)
    gemm_mma<768, 512, 256, float, __half><<<dim3(8, 6, BATCH), 256, GEMM_SMEM>>>(
        w_qkv, x, b_qkv, (__half*)qkvp, 0.17677669529663687f);

    // 2) fp16 fused attention (head-softmax), q-tile 64, 512 threads
    attn_mma<<<dim3(16, BATCH), 512, ATTN_SMEM>>>((const __half*)qkvp,
                                                  (__half*)afp);

    // 3) output projection (fp16 mma; fp16 input; fp32 output)
    gemm_mma<512, 256, 0, __half, float><<<dim3(8, 4, BATCH), 256, GEMM_SMEM>>>(
        w_attn, (const __half*)afp, b_attn, out, 1.0f);
}

// round 8
// speedup vs baseline: 5.6645x; 1.0327x over previous
#include <cuda_runtime.h>
#include <cuda_fp16.h>
#include <cstdint>

#define BATCH 8
#define HW    1024
#define QKV_CH 768

// Scratch (device globals; no allocation allowed)
__device__ __half g_qkvh[BATCH * QKV_CH * HW];  // [b][768][1024] fp16
__device__ __half g_afh [BATCH * 256   * HW];   // attention out (scrambled layout) fp16

// ===========================================================================
// helpers
// ===========================================================================
__device__ __forceinline__ uint32_t smem_u32(const void* p) {
    uint32_t a;
    asm("{ .reg .u64 t; cvta.to.shared.u64 t, %1; cvt.u32.u64 %0, t; }"
        : "=r"(a) : "l"(p));
    return a;
}
__device__ __forceinline__ void mma16816(float* c, const uint32_t* a, const uint32_t* b) {
    asm volatile("mma.sync.aligned.m16n8k16.row.col.f32.f16.f16.f32 "
        "{%0,%1,%2,%3}, {%4,%5,%6,%7}, {%8,%9}, {%0,%1,%2,%3};"
        : "+f"(c[0]), "+f"(c[1]), "+f"(c[2]), "+f"(c[3])
        : "r"(a[0]), "r"(a[1]), "r"(a[2]), "r"(a[3]), "r"(b[0]), "r"(b[1]));
}
__device__ __forceinline__ void ldsm_x4(uint32_t* r, uint32_t addr) {
    asm volatile("ldmatrix.sync.aligned.m8n8.x4.shared.b16 {%0,%1,%2,%3}, [%4];"
        : "=r"(r[0]), "=r"(r[1]), "=r"(r[2]), "=r"(r[3]) : "r"(addr));
}
__device__ __forceinline__ void ldsm_x4t(uint32_t* r, uint32_t addr) {
    asm volatile("ldmatrix.sync.aligned.m8n8.x4.trans.shared.b16 {%0,%1,%2,%3}, [%4];"
        : "=r"(r[0]), "=r"(r[1]), "=r"(r[2]), "=r"(r[3]) : "r"(addr));
}
__device__ __forceinline__ uint32_t pack_h2(float lo, float hi) {
    __half2 h = __floats2half2_rn(lo, hi);
    return *reinterpret_cast<uint32_t*>(&h);
}
__device__ __forceinline__ uint32_t hh2pack(__half a, __half b) {
    __half2 h = __halves2half2(a, b);
    return *reinterpret_cast<uint32_t*>(&h);
}
__device__ __forceinline__ float2 h2f2(uint32_t u) {
    __half2 h = *reinterpret_cast<__half2*>(&u);
    return __half22float2(h);
}
#define CP_ASYNC16(dst, src) \
    asm volatile("cp.async.cg.shared.global [%0], [%1], 16;" \
                 :: "r"(dst), "l"(src) : "memory")
#define CP_COMMIT() asm volatile("cp.async.commit_group;" ::: "memory")
#define CP_WAIT1()  asm volatile("cp.async.wait_group 1;" ::: "memory")
#define GROUP_BAR(id) asm volatile("bar.sync %0, 256;" :: "r"(id) : "memory")

// packed fp32x2
typedef unsigned long long ull;
__device__ __forceinline__ ull fma2v(ull a, ull b, ull c) {
    ull d; asm("fma.rn.f32x2 %0, %1, %2, %3;" : "=l"(d) : "l"(a), "l"(b), "l"(c)); return d;
}
__device__ __forceinline__ ull mul2v(ull a, ull b) {
    ull d; asm("mul.rn.f32x2 %0, %1, %2;" : "=l"(d) : "l"(a), "l"(b)); return d;
}
__device__ __forceinline__ ull add2v(ull a, ull b) {
    ull d; asm("add.rn.f32x2 %0, %1, %2;" : "=l"(d) : "l"(a), "l"(b)); return d;
}
__device__ __forceinline__ ull dup2(float v) {
    ull r; uint32_t u = __float_as_uint(v);
    asm("mov.b64 %0, {%1, %1};" : "=l"(r) : "r"(u));
    return r;
}
__device__ __forceinline__ ull pk2(float x, float y) {
    ull r; uint32_t a = __float_as_uint(x), b = __float_as_uint(y);
    asm("mov.b64 %0, {%1, %2};" : "=l"(r) : "r"(a), "r"(b));
    return r;
}
__device__ __forceinline__ float frcp(float x) {
    float r = __int_as_float(0x7EF311C3 - __float_as_int(x));
    r = r * (2.0f - x * r);
    r = r * (2.0f - x * r);
    r = r * (2.0f - x * r);
    return r;
}
__device__ __forceinline__ void exp2pairf(ull l, float& elo, float& ehi) {
    const ull LOG2E2 = dup2(1.4426950408889634f);
    const ull MAGIC2 = dup2(12582912.0f);
    const ull NMAGIC2 = dup2(-12582912.0f);
    const ull NONE2  = dup2(-1.0f);
    ull y  = mul2v(l, LOG2E2);
    ull tt = add2v(y, MAGIC2);
    ull nn2 = add2v(tt, NMAGIC2);
    ull f  = fma2v(nn2, NONE2, y);
    ull pe = fma2v(dup2(9.6183290401232e-3f), f, dup2(5.550410866482158e-2f));
    pe = fma2v(pe, f, dup2(2.402265069591007e-1f));
    pe = fma2v(pe, f, dup2(6.931471805599453e-1f));
    pe = fma2v(pe, f, dup2(1.0f));
    uint32_t tlo, thi, plo, phi;
    asm("mov.b64 {%0,%1}, %2;" : "=r"(tlo), "=r"(thi) : "l"(tt));
    asm("mov.b64 {%0,%1}, %2;" : "=r"(plo), "=r"(phi) : "l"(pe));
    elo = __int_as_float((int)((tlo << 23) + plo));
    ehi = __int_as_float((int)((thi << 23) + phi));
}

// ===========================================================================
// fp16 mma.sync GEMM (unchanged)
// ===========================================================================
static constexpr int ASZ = 128 * 80;
static constexpr int BSZ = 32 * 272;
static constexpr int GEMM_SMEM = 2 * (ASZ + BSZ);

template<int M, int K, int SCALE_ROWS, typename TX, typename TY>
__global__ __launch_bounds__(256, 2)
void gemm_mma(const float* __restrict__ W, const TX* __restrict__ X,
              const float* __restrict__ bias, TY* __restrict__ Y,
              float scaleVal)
{
    extern __shared__ char smraw[];
    const uint32_t smb = smem_u32(smraw);

    const int t    = threadIdx.x;
    const int lane = t & 31;
    const int wid  = t >> 5;
    const int g    = lane >> 2;
    const int t4   = lane & 3;
    const int wm   = (wid & 1) * 64;
    const int wn   = (wid >> 1) * 32;
    const int b    = blockIdx.z;
    const int m0   = blockIdx.y * 128;
    const int n0   = blockIdx.x * 128;
    const TX* Xb = X + (size_t)b * K * 1024;
    TY*       Yb = Y + (size_t)b * M * 1024;

    const int r16 = lane & 15;
    const int c8  = (lane >> 4) * 8;
    const uint32_t aAddr = smb + (wm + r16) * 80 + c8 * 2;
    const uint32_t bAddr = smb + 2 * ASZ + r16 * 272 + (wn + c8) * 2;

    const int am = t >> 3;
    const int ak = (t & 7) * 4;
    const int bk = t >> 5;
    const int bn = (t & 31) * 4;

    float4 aw[4];
    float4 bwf[4];
    uint2  bwh[4];
    float acc[4][4][4];
#pragma unroll
    for (int i = 0; i < 4; i++)
#pragma unroll
        for (int j = 0; j < 4; j++)
#pragma unroll
            for (int q = 0; q < 4; q++) acc[i][j][q] = 0.f;

    auto LOADR = [&](int kc) {
#pragma unroll
        for (int c = 0; c < 4; c++)
            aw[c] = *(const float4*)&W[(size_t)(m0 + am + c * 32) * K + kc * 32 + ak];
#pragma unroll
        for (int c = 0; c < 4; c++) {
            if constexpr (sizeof(TX) == 2)
                bwh[c] = *(const uint2*)&Xb[(size_t)(kc * 32 + bk + c * 8) * 1024 + n0 + bn];
            else
                bwf[c] = *(const float4*)&Xb[(size_t)(kc * 32 + bk + c * 8) * 1024 + n0 + bn];
        }
    };
    auto STORE = [&](int st) {
        char* A  = smraw + st * ASZ;
        char* Bm = smraw + 2 * ASZ + st * BSZ;
#pragma unroll
        for (int c = 0; c < 4; c++) {
            uint2 v;
            v.x = pack_h2(aw[c].x, aw[c].y);
            v.y = pack_h2(aw[c].z, aw[c].w);
            *(uint2*)(A + (am + c * 32) * 80 + ak * 2) = v;
        }
#pragma unroll
        for (int c = 0; c < 4; c++) {
            if constexpr (sizeof(TX) == 2) {
                *(uint2*)(Bm + (bk + c * 8) * 272 + bn * 2) = bwh[c];
            } else {
                uint2 v;
                v.x = pack_h2(bwf[c].x, bwf[c].y);
                v.y = pack_h2(bwf[c].z, bwf[c].w);
                *(uint2*)(Bm + (bk + c * 8) * 272 + bn * 2) = v;
            }
        }
    };

    const int NC = K / 32;
    LOADR(0);
    STORE(0);
    __syncthreads();

    for (int kc = 0; kc < NC; kc++) {
        if (kc + 1 < NC) LOADR(kc + 1);

        const uint32_t aB = aAddr + (kc & 1) * ASZ;
        const uint32_t bB = bAddr + (kc & 1) * BSZ;
#pragma unroll
        for (int s = 0; s < 2; s++) {
            uint32_t afr[4][4], bfr[2][4];
#pragma unroll
            for (int mf = 0; mf < 4; mf++)
                ldsm_x4(afr[mf], aB + mf * 16 * 80 + s * 32);
#pragma unroll
            for (int np = 0; np < 2; np++)
                ldsm_x4t(bfr[np], bB + np * 32 + s * 16 * 272);
#pragma unroll
            for (int mf = 0; mf < 4; mf++)
#pragma unroll
                for (int np = 0; np < 2; np++) {
                    mma16816(acc[mf][2 * np],     afr[mf], bfr[np] + 0);
                    mma16816(acc[mf][2 * np + 1], afr[mf], bfr[np] + 2);
                }
        }
        if (kc + 1 < NC) STORE((kc + 1) & 1);
        __syncthreads();
    }

#pragma unroll
    for (int mf = 0; mf < 4; mf++) {
        int r0 = m0 + wm + mf * 16 + g;
        int r1 = r0 + 8;
        float b0v = bias[r0], b1v = bias[r1];
        float s0 = (SCALE_ROWS > 0 && r0 < SCALE_ROWS) ? scaleVal : 1.f;
        float s1 = (SCALE_ROWS > 0 && r1 < SCALE_ROWS) ? scaleVal : 1.f;
#pragma unroll
        for (int nf = 0; nf < 4; nf++) {
            int nc = n0 + wn + nf * 8 + 2 * t4;
            if constexpr (sizeof(TY) == 2) {
                *(uint32_t*)&Yb[(size_t)r0 * 1024 + nc] =
                    pack_h2((acc[mf][nf][0] + b0v) * s0, (acc[mf][nf][1] + b0v) * s0);
                *(uint32_t*)&Yb[(size_t)r1 * 1024 + nc] =
                    pack_h2((acc[mf][nf][2] + b1v) * s1, (acc[mf][nf][3] + b1v) * s1);
            } else {
                float2 v0, v1;
                v0.x = (acc[mf][nf][0] + b0v) * s0;
                v0.y = (acc[mf][nf][1] + b0v) * s0;
                v1.x = (acc[mf][nf][2] + b1v) * s1;
                v1.y = (acc[mf][nf][3] + b1v) * s1;
                *(float2*)&Yb[(size_t)r0 * 1024 + nc] = v0;
                *(float2*)&Yb[(size_t)r1 * 1024 + nc] = v1;
            }
        }
    }
}

// ===========================================================================
// fp16 fused attention, q-tile 64, 512 threads, software-pipelined softmax:
// phase A of iter kt = AV(kt-1) + S(kt)+exp(kt); group barrier (per q-half);
// phase B = cross-head denom+rescale(kt). V triple-buffered (AV reads kt-1
// while cp.async writes kt+1), Es double-buffered. Softmax across the 8
// HEADS. Output in the reference's scrambled flat-reshape layout (fp16).
// ===========================================================================
static constexpr int KS_OFF = 0;        // 2 x 20480
static constexpr int VS_OFF = 40960;    // 3 x 20480
static constexpr int ES_OFF = 102400;   // 2 x 40960  ([2qh][8n][32q][40])
static constexpr int ATTN_SMEM = 184320;

__global__ __launch_bounds__(512, 1)
void attn_mma(const __half* __restrict__ qkvh, __half* __restrict__ af)
{
    extern __shared__ char smraw[];
    const uint32_t smb = smem_u32(smraw);
    __half* EsH = (__half*)(smraw + ES_OFF);

    const int b    = blockIdx.y;
    const int qt   = blockIdx.x;           // 16 tiles of 64 queries
    const int q0   = qt * 64;
    const int t    = threadIdx.x;
    const int lane = t & 31;
    const int w    = t >> 5;               // 16 warps
    const int n    = w & 7;                // head
    const int qh   = w >> 3;               // q-half (0/1); group = threads qh*256..
    const int tg   = t & 255;              // thread id within q-half group
    const int g    = lane >> 2;
    const int t4   = lane & 3;

    const int r16 = lane & 15;
    const int c8  = (lane >> 4) * 8;
    const int r2  = (lane & 7) + (lane >> 4) * 8;
    const int c2  = ((lane >> 3) & 1) * 8;

    const __half* qbh = qkvh + (size_t)b * QKV_CH * HW;

    // ---- preload Q A-fragments for this warp's 32-q subtile ----
    uint32_t qa[2][2][4];
    {
        const int qg = q0 + qh * 32 + g;
#pragma unroll
        for (int mf = 0; mf < 2; mf++)
#pragma unroll
            for (int s = 0; s < 2; s++) {
                int d0 = s * 16 + 2 * t4;
                const __half* ra = qbh + (size_t)(n * 32 + d0) * HW;
                const __half* rb = qbh + (size_t)(n * 32 + d0 + 1) * HW;
                const __half* rc = qbh + (size_t)(n * 32 + d0 + 8) * HW;
                const __half* rd = qbh + (size_t)(n * 32 + d0 + 9) * HW;
                int qq = qg + mf * 16;
                qa[mf][s][0] = hh2pack(ra[qq],     rb[qq]);
                qa[mf][s][1] = hh2pack(ra[qq + 8], rb[qq + 8]);
                qa[mf][s][2] = hh2pack(rc[qq],     rd[qq]);
                qa[mf][s][3] = hh2pack(rc[qq + 8], rd[qq + 8]);
            }
    }

    float oacc[2][4][4];
#pragma unroll
    for (int i = 0; i < 2; i++)
#pragma unroll
        for (int j = 0; j < 4; j++)
#pragma unroll
            for (int q = 0; q < 4; q++) oacc[i][j][q] = 0.f;

    const uint32_t sbK = smb + KS_OFF + ((n * 32 + r16) * 40 + c8) * 2;
    const uint32_t sbV = smb + VS_OFF + ((n * 32 + r16) * 40 + c8) * 2;
    const uint32_t sbE = smb + ES_OFF + (((qh * 8 + n) * 32 + r2) * 40 + c2) * 2;

    // prefetch one 32-wide k-tile: K -> buf[kt&1], V -> buf[kt%3]
    auto PREFETCH = [&](int kt2) {
        if (kt2 <= 31) {
            const int k0   = kt2 * 32;
            const int kbo  = (kt2 & 1) * 20480;
            const int vbo  = (kt2 % 3) * 20480;
#pragma unroll
            for (int c = 0; c < 2; c++) {
                int idx = c * 512 + t;
                int row = idx >> 2;
                int col = (idx & 3) * 8;
                CP_ASYNC16(smb + KS_OFF + kbo + row * 80 + col * 2,
                           qbh + (size_t)(256 + row) * HW + k0 + col);
                CP_ASYNC16(smb + VS_OFF + vbo + row * 80 + col * 2,
                           qbh + (size_t)(512 + row) * HW + k0 + col);
            }
        }
        CP_COMMIT();
    };

    // AV for tile kt2 (reads Vs[kt2%3] and rescaled Es[kt2&1])
    auto AV = [&](int kt2) {
        const uint32_t vbo = (uint32_t)(kt2 % 3) * 20480;
        const uint32_t ebo = (uint32_t)(kt2 & 1) * 40960;
#pragma unroll
        for (int ks = 0; ks < 2; ks++) {
            uint32_t va[2][4], wb[2][4];
            ldsm_x4(va[0], sbV + vbo + ks * 32);
            ldsm_x4(va[1], sbV + vbo + 16 * 80 + ks * 32);
            ldsm_x4(wb[0], sbE + ebo + ks * 32);
            ldsm_x4(wb[1], sbE + ebo + 16 * 80 + ks * 32);
#pragma unroll
            for (int mf = 0; mf < 2; mf++)
#pragma unroll
                for (int np = 0; np < 2; np++) {
                    mma16816(oacc[mf][2 * np],     va[mf], wb[np] + 0);
                    mma16816(oacc[mf][2 * np + 1], va[mf], wb[np] + 2);
                }
        }
    };

    PREFETCH(0);

    for (int kt = 0; kt < 32; kt++) {
        __syncthreads();           // prev iter fully drained: buffers rotate safely
        PREFETCH(kt + 1);          // overlaps with this iteration's compute
        CP_WAIT1();                // this thread's group kt landed
        __syncthreads();           // ... and all threads'

        // ---- phase A: AV(kt-1) (independent) + S(kt)+exp(kt) ----
        if (kt > 0) AV(kt - 1);

        const uint32_t kbo = (kt & 1) * 20480;
        const uint32_t epo = (kt & 1) * 40960;
        __half* EsN = (__half*)(smraw + ES_OFF + epo) + (qh * 8 + n) * 32 * 40;
#pragma unroll
        for (int np = 0; np < 2; np++) {
            float sacc[2][2][4];
#pragma unroll
            for (int mf = 0; mf < 2; mf++)
#pragma unroll
                for (int nn = 0; nn < 2; nn++)
#pragma unroll
                    for (int q = 0; q < 4; q++) sacc[mf][nn][q] = 0.f;
#pragma unroll
            for (int s = 0; s < 2; s++) {
                uint32_t bk[4];
                ldsm_x4t(bk, sbK + kbo + s * 16 * 80 + np * 32);
#pragma unroll
                for (int mf = 0; mf < 2; mf++) {
                    mma16816(sacc[mf][0], qa[mf][s], bk + 0);
                    mma16816(sacc[mf][1], qa[mf][s], bk + 2);
                }
            }
#pragma unroll
            for (int mf = 0; mf < 2; mf++)
#pragma unroll
                for (int nn = 0; nn < 2; nn++) {
                    int kp = (np * 2 + nn) * 8 + 2 * t4;
                    int qr = mf * 16 + g;
                    float e0, e1, e2, e3;
                    exp2pairf(pk2(sacc[mf][nn][0], sacc[mf][nn][1]), e0, e1);
                    exp2pairf(pk2(sacc[mf][nn][2], sacc[mf][nn][3]), e2, e3);
                    *(uint32_t*)(EsN + qr * 40 + kp)       = pack_h2(e0, e1);
                    *(uint32_t*)(EsN + (qr + 8) * 40 + kp) = pack_h2(e2, e3);
                }
        }

        GROUP_BAR(qh + 1);   // only this q-half's 8 heads must be complete

        // ---- phase B: cross-head denom + Newton recip + rescale (own qh) ----
        {
            __half* EsP = (__half*)(smraw + ES_OFF + epo);
#pragma unroll
            for (int j = 0; j < 2; j++) {
                int P  = (tg << 1) | j;          // 512 (q, kpos-pair) slots per group
                int qr = P >> 4;
                int kp = (P & 15) << 1;
                __half* base = EsP + ((qh * 8) * 32 + qr) * 40 + kp;
                uint32_t ev[8];
                float sx = 0.f, sy = 0.f;
#pragma unroll
                for (int n2 = 0; n2 < 8; n2++) {
                    ev[n2] = *(uint32_t*)(base + n2 * (32 * 40));
                    float2 f = h2f2(ev[n2]);
                    sx += f.x; sy += f.y;
                }
                float rx = frcp(sx), ry = frcp(sy);
#pragma unroll
                for (int n2 = 0; n2 < 8; n2++) {
                    float2 f = h2f2(ev[n2]);
                    *(uint32_t*)(base + n2 * (32 * 40)) = pack_h2(f.x * rx, f.y * ry);
                }
            }
        }
    }

    // drain: AV for the last tile (rescale(31) by own group must be visible)
    GROUP_BAR(qh + 1);
    AV(31);

    // ---- epilogue: scrambled flat-reshape layout, fp16 ----
    __half* ob = af + ((size_t)(b * 256 + n * 32 + qt * 2 + qh)) * 1024;
#pragma unroll
    for (int mf = 0; mf < 2; mf++)
#pragma unroll
        for (int nf = 0; nf < 4; nf++) {
            int d = 16 * mf + g;
            int q = 8 * nf + 2 * t4;
            ob[q * 32 + d]           = __float2half_rn(oacc[mf][nf][0]);
            ob[(q + 1) * 32 + d]     = __float2half_rn(oacc[mf][nf][1]);
            ob[q * 32 + d + 8]       = __float2half_rn(oacc[mf][nf][2]);
            ob[(q + 1) * 32 + d + 8] = __float2half_rn(oacc[mf][nf][3]);
        }
}

// ---------------------------------------------------------------------------
extern "C" void kernel_launch(void* const* d_in, const int* in_sizes, int n_in,
                              void* d_out, int out_size)
{
    const float* x      = (const float*)d_in[0];   // [8,512,32,32]
    const float* w_qkv  = (const float*)d_in[1];   // [768,512]
    const float* b_qkv  = (const float*)d_in[2];   // [768]
    const float* w_attn = (const float*)d_in[3];   // [512,256]
    const float* b_attn = (const float*)d_in[4];   // [512]
    float* out = (float*)d_out;                    // [8,512,32,32]

    void* qkvp = nullptr;
    void* afp  = nullptr;
    cudaGetSymbolAddress(&qkvp, g_qkvh);
    cudaGetSymbolAddress(&afp,  g_afh);

    cudaFuncSetAttribute((const void*)gemm_mma<768, 512, 256, float, __half>,
                         cudaFuncAttributeMaxDynamicSharedMemorySize, GEMM_SMEM);
    cudaFuncSetAttribute((const void*)gemm_mma<512, 256, 0, __half, float>,
                         cudaFuncAttributeMaxDynamicSharedMemorySize, GEMM_SMEM);
    cudaFuncSetAttribute((const void*)attn_mma,
                         cudaFuncAttributeMaxDynamicSharedMemorySize, ATTN_SMEM);

    // 1) QKV projection (fp16 mma; bias; q rows scaled; fp16 output)
    gemm_mma<768, 512, 256, float, __half><<<dim3(8, 6, BATCH), 256, GEMM_SMEM>>>(
        w_qkv, x, b_qkv, (__half*)qkvp, 0.17677669529663687f);

    // 2) fp16 fused attention (head-softmax), pipelined softmax chain
    attn_mma<<<dim3(16, BATCH), 512, ATTN_SMEM>>>((const __half*)qkvp,
                                                  (__half*)afp);

    // 3) output projection (fp16 mma; fp16 input; fp32 output)
    gemm_mma<512, 256, 0, __half, float><<<dim3(8, 4, BATCH), 256, GEMM_SMEM>>>(
        w_attn, (const __half*)afp, b_attn, out, 1.0f);
}

// round 9
// speedup vs baseline: 5.9190x; 1.0449x over previous
#include <cuda_runtime.h>
#include <cuda_fp16.h>
#include <cstdint>

#define BATCH 8
#define HW    1024
#define QKV_CH 768

// Scratch (device globals; no allocation allowed)
__device__ __half g_qkvh[BATCH * QKV_CH * HW];  // [b][768][1024] fp16
__device__ __half g_afh [BATCH * 256   * HW];   // attention out (scrambled layout) fp16

// ===========================================================================
// helpers
// ===========================================================================
__device__ __forceinline__ uint32_t smem_u32(const void* p) {
    uint32_t a;
    asm("{ .reg .u64 t; cvta.to.shared.u64 t, %1; cvt.u32.u64 %0, t; }"
        : "=r"(a) : "l"(p));
    return a;
}
__device__ __forceinline__ void mma16816(float* c, const uint32_t* a, const uint32_t* b) {
    asm volatile("mma.sync.aligned.m16n8k16.row.col.f32.f16.f16.f32 "
        "{%0,%1,%2,%3}, {%4,%5,%6,%7}, {%8,%9}, {%0,%1,%2,%3};"
        : "+f"(c[0]), "+f"(c[1]), "+f"(c[2]), "+f"(c[3])
        : "r"(a[0]), "r"(a[1]), "r"(a[2]), "r"(a[3]), "r"(b[0]), "r"(b[1]));
}
__device__ __forceinline__ void ldsm_x4(uint32_t* r, uint32_t addr) {
    asm volatile("ldmatrix.sync.aligned.m8n8.x4.shared.b16 {%0,%1,%2,%3}, [%4];"
        : "=r"(r[0]), "=r"(r[1]), "=r"(r[2]), "=r"(r[3]) : "r"(addr));
}
__device__ __forceinline__ void ldsm_x4t(uint32_t* r, uint32_t addr) {
    asm volatile("ldmatrix.sync.aligned.m8n8.x4.trans.shared.b16 {%0,%1,%2,%3}, [%4];"
        : "=r"(r[0]), "=r"(r[1]), "=r"(r[2]), "=r"(r[3]) : "r"(addr));
}
__device__ __forceinline__ uint32_t pack_h2(float lo, float hi) {
    __half2 h = __floats2half2_rn(lo, hi);
    return *reinterpret_cast<uint32_t*>(&h);
}
__device__ __forceinline__ uint32_t hh2pack(__half a, __half b) {
    __half2 h = __halves2half2(a, b);
    return *reinterpret_cast<uint32_t*>(&h);
}
__device__ __forceinline__ float2 h2f2(uint32_t u) {
    __half2 h = *reinterpret_cast<__half2*>(&u);
    return __half22float2(h);
}
#define CP_ASYNC16(dst, src) \
    asm volatile("cp.async.cg.shared.global [%0], [%1], 16;" \
                 :: "r"(dst), "l"(src) : "memory")
#define CP_COMMIT() asm volatile("cp.async.commit_group;" ::: "memory")
#define CP_WAIT1()  asm volatile("cp.async.wait_group 1;" ::: "memory")
#define GROUP_BAR64(id) asm volatile("bar.sync %0, 64;" :: "r"(id) : "memory")

// packed fp32x2
typedef unsigned long long ull;
__device__ __forceinline__ ull fma2v(ull a, ull b, ull c) {
    ull d; asm("fma.rn.f32x2 %0, %1, %2, %3;" : "=l"(d) : "l"(a), "l"(b), "l"(c)); return d;
}
__device__ __forceinline__ ull mul2v(ull a, ull b) {
    ull d; asm("mul.rn.f32x2 %0, %1, %2;" : "=l"(d) : "l"(a), "l"(b)); return d;
}
__device__ __forceinline__ ull add2v(ull a, ull b) {
    ull d; asm("add.rn.f32x2 %0, %1, %2;" : "=l"(d) : "l"(a), "l"(b)); return d;
}
__device__ __forceinline__ ull dup2(float v) {
    ull r; uint32_t u = __float_as_uint(v);
    asm("mov.b64 %0, {%1, %1};" : "=l"(r) : "r"(u));
    return r;
}
__device__ __forceinline__ ull pk2(float x, float y) {
    ull r; uint32_t a = __float_as_uint(x), b = __float_as_uint(y);
    asm("mov.b64 %0, {%1, %2};" : "=l"(r) : "r"(a), "r"(b));
    return r;
}
// MUFU reciprocal (~1 ulp)
__device__ __forceinline__ float frcpa(float x) {
    float r; asm("rcp.approx.f32 %0, %1;" : "=f"(r) : "f"(x)); return r;
}
__device__ __forceinline__ void exp2pairf(ull l, float& elo, float& ehi) {
    const ull LOG2E2 = dup2(1.4426950408889634f);
    const ull MAGIC2 = dup2(12582912.0f);
    const ull NMAGIC2 = dup2(-12582912.0f);
    const ull NONE2  = dup2(-1.0f);
    ull y  = mul2v(l, LOG2E2);
    ull tt = add2v(y, MAGIC2);
    ull nn2 = add2v(tt, NMAGIC2);
    ull f  = fma2v(nn2, NONE2, y);
    ull pe = fma2v(dup2(9.6183290401232e-3f), f, dup2(5.550410866482158e-2f));
    pe = fma2v(pe, f, dup2(2.402265069591007e-1f));
    pe = fma2v(pe, f, dup2(6.931471805599453e-1f));
    pe = fma2v(pe, f, dup2(1.0f));
    uint32_t tlo, thi, plo, phi;
    asm("mov.b64 {%0,%1}, %2;" : "=r"(tlo), "=r"(thi) : "l"(tt));
    asm("mov.b64 {%0,%1}, %2;" : "=r"(plo), "=r"(phi) : "l"(pe));
    elo = __int_as_float((int)((tlo << 23) + plo));
    ehi = __int_as_float((int)((thi << 23) + phi));
}

// ===========================================================================
// fp16 mma.sync GEMM (unchanged from round 8)
// ===========================================================================
static constexpr int ASZ = 128 * 80;
static constexpr int BSZ = 32 * 272;
static constexpr int GEMM_SMEM = 2 * (ASZ + BSZ);

template<int M, int K, int SCALE_ROWS, typename TX, typename TY>
__global__ __launch_bounds__(256, 2)
void gemm_mma(const float* __restrict__ W, const TX* __restrict__ X,
              const float* __restrict__ bias, TY* __restrict__ Y,
              float scaleVal)
{
    extern __shared__ char smraw[];
    const uint32_t smb = smem_u32(smraw);

    const int t    = threadIdx.x;
    const int lane = t & 31;
    const int wid  = t >> 5;
    const int g    = lane >> 2;
    const int t4   = lane & 3;
    const int wm   = (wid & 1) * 64;
    const int wn   = (wid >> 1) * 32;
    const int b    = blockIdx.z;
    const int m0   = blockIdx.y * 128;
    const int n0   = blockIdx.x * 128;
    const TX* Xb = X + (size_t)b * K * 1024;
    TY*       Yb = Y + (size_t)b * M * 1024;

    const int r16 = lane & 15;
    const int c8  = (lane >> 4) * 8;
    const uint32_t aAddr = smb + (wm + r16) * 80 + c8 * 2;
    const uint32_t bAddr = smb + 2 * ASZ + r16 * 272 + (wn + c8) * 2;

    const int am = t >> 3;
    const int ak = (t & 7) * 4;
    const int bk = t >> 5;
    const int bn = (t & 31) * 4;

    float4 aw[4];
    float4 bwf[4];
    uint2  bwh[4];
    float acc[4][4][4];
#pragma unroll
    for (int i = 0; i < 4; i++)
#pragma unroll
        for (int j = 0; j < 4; j++)
#pragma unroll
            for (int q = 0; q < 4; q++) acc[i][j][q] = 0.f;

    auto LOADR = [&](int kc) {
#pragma unroll
        for (int c = 0; c < 4; c++)
            aw[c] = *(const float4*)&W[(size_t)(m0 + am + c * 32) * K + kc * 32 + ak];
#pragma unroll
        for (int c = 0; c < 4; c++) {
            if constexpr (sizeof(TX) == 2)
                bwh[c] = *(const uint2*)&Xb[(size_t)(kc * 32 + bk + c * 8) * 1024 + n0 + bn];
            else
                bwf[c] = *(const float4*)&Xb[(size_t)(kc * 32 + bk + c * 8) * 1024 + n0 + bn];
        }
    };
    auto STORE = [&](int st) {
        char* A  = smraw + st * ASZ;
        char* Bm = smraw + 2 * ASZ + st * BSZ;
#pragma unroll
        for (int c = 0; c < 4; c++) {
            uint2 v;
            v.x = pack_h2(aw[c].x, aw[c].y);
            v.y = pack_h2(aw[c].z, aw[c].w);
            *(uint2*)(A + (am + c * 32) * 80 + ak * 2) = v;
        }
#pragma unroll
        for (int c = 0; c < 4; c++) {
            if constexpr (sizeof(TX) == 2) {
                *(uint2*)(Bm + (bk + c * 8) * 272 + bn * 2) = bwh[c];
            } else {
                uint2 v;
                v.x = pack_h2(bwf[c].x, bwf[c].y);
                v.y = pack_h2(bwf[c].z, bwf[c].w);
                *(uint2*)(Bm + (bk + c * 8) * 272 + bn * 2) = v;
            }
        }
    };

    const int NC = K / 32;
    LOADR(0);
    STORE(0);
    __syncthreads();

    for (int kc = 0; kc < NC; kc++) {
        if (kc + 1 < NC) LOADR(kc + 1);

        const uint32_t aB = aAddr + (kc & 1) * ASZ;
        const uint32_t bB = bAddr + (kc & 1) * BSZ;
#pragma unroll
        for (int s = 0; s < 2; s++) {
            uint32_t afr[4][4], bfr[2][4];
#pragma unroll
            for (int mf = 0; mf < 4; mf++)
                ldsm_x4(afr[mf], aB + mf * 16 * 80 + s * 32);
#pragma unroll
            for (int np = 0; np < 2; np++)
                ldsm_x4t(bfr[np], bB + np * 32 + s * 16 * 272);
#pragma unroll
            for (int mf = 0; mf < 4; mf++)
#pragma unroll
                for (int np = 0; np < 2; np++) {
                    mma16816(acc[mf][2 * np],     afr[mf], bfr[np] + 0);
                    mma16816(acc[mf][2 * np + 1], afr[mf], bfr[np] + 2);
                }
        }
        if (kc + 1 < NC) STORE((kc + 1) & 1);
        __syncthreads();
    }

#pragma unroll
    for (int mf = 0; mf < 4; mf++) {
        int r0 = m0 + wm + mf * 16 + g;
        int r1 = r0 + 8;
        float b0v = bias[r0], b1v = bias[r1];
        float s0 = (SCALE_ROWS > 0 && r0 < SCALE_ROWS) ? scaleVal : 1.f;
        float s1 = (SCALE_ROWS > 0 && r1 < SCALE_ROWS) ? scaleVal : 1.f;
#pragma unroll
        for (int nf = 0; nf < 4; nf++) {
            int nc = n0 + wn + nf * 8 + 2 * t4;
            if constexpr (sizeof(TY) == 2) {
                *(uint32_t*)&Yb[(size_t)r0 * 1024 + nc] =
                    pack_h2((acc[mf][nf][0] + b0v) * s0, (acc[mf][nf][1] + b0v) * s0);
                *(uint32_t*)&Yb[(size_t)r1 * 1024 + nc] =
                    pack_h2((acc[mf][nf][2] + b1v) * s1, (acc[mf][nf][3] + b1v) * s1);
            } else {
                float2 v0, v1;
                v0.x = (acc[mf][nf][0] + b0v) * s0;
                v0.y = (acc[mf][nf][1] + b0v) * s0;
                v1.x = (acc[mf][nf][2] + b1v) * s1;
                v1.y = (acc[mf][nf][3] + b1v) * s1;
                *(float2*)&Yb[(size_t)r0 * 1024 + nc] = v0;
                *(float2*)&Yb[(size_t)r1 * 1024 + nc] = v1;
            }
        }
    }
}

// ===========================================================================
// fp16 fused attention, IN-REGISTER head softmax.
// Block = 256 threads = 8 warps = 4 warp-pairs. Pair p owns queries
// [qt*64 + p*16, +16); warp (p, wip) owns heads wip*4..wip*4+3 for those q.
// Per 32-wide k-tile: S via mma (Q in regs, K^T ldsm.trans) -> exp in-register
// -> partial denominators summed across own 4 heads in REGISTERS -> tiny
// pair exchange (smem + 64-thread named barrier) -> rcp (MUFU) -> W repacked
// in-register as AV A-frags (flash-attn P-reuse) -> O += W V (V as B-frags).
// K/V triple-buffered cp.async, ONE __syncthreads per tile. Softmax is
// across the 8 HEADS (reference axis=1). Output: scrambled reshape, fp16.
// ===========================================================================
static constexpr int KS_OFF = 0;                    // 3 x 20480
static constexpr int VS_OFF = 3 * 20480;            // 3 x 20480
static constexpr int PD_OFF = 6 * 20480;            // 8 x 2176
static constexpr int ATTN_SMEM = PD_OFF + 8 * 2176; // 140288 B

__global__ __launch_bounds__(256, 1)
void attn_mma(const __half* __restrict__ qkvh, __half* __restrict__ af)
{
    extern __shared__ char smraw[];
    const uint32_t smb = smem_u32(smraw);

    const int b    = blockIdx.y;
    const int qt   = blockIdx.x;           // 16 tiles of 64 queries
    const int t    = threadIdx.x;
    const int lane = t & 31;
    const int w    = t >> 5;               // 8 warps
    const int p    = w >> 1;               // pair 0..3
    const int wip  = w & 1;                // 0: heads 0-3, 1: heads 4-7
    const int g    = lane >> 2;
    const int t4   = lane & 3;

    const int r16 = lane & 15;
    const int c8  = (lane >> 4) * 8;
    const int r2  = (lane & 7) + (lane >> 4) * 8;
    const int c2  = ((lane >> 3) & 1) * 8;

    const int qW = qt * 64 + p * 16;       // this pair's 16-query slice
    const __half* qbh = qkvh + (size_t)b * QKV_CH * HW;

    // ---- preload Q A-fragments for 4 heads (reused all 32 tiles) ----
    uint32_t qa[4][2][4];
#pragma unroll
    for (int h = 0; h < 4; h++) {
        const int gh = wip * 4 + h;
#pragma unroll
        for (int s = 0; s < 2; s++) {
            int d0 = s * 16 + 2 * t4;
            const __half* ra = qbh + (size_t)(gh * 32 + d0) * HW;
            const __half* rb = qbh + (size_t)(gh * 32 + d0 + 1) * HW;
            const __half* rc = qbh + (size_t)(gh * 32 + d0 + 8) * HW;
            const __half* rd = qbh + (size_t)(gh * 32 + d0 + 9) * HW;
            int qq = qW + g;
            qa[h][s][0] = hh2pack(ra[qq],     rb[qq]);
            qa[h][s][1] = hh2pack(ra[qq + 8], rb[qq + 8]);
            qa[h][s][2] = hh2pack(rc[qq],     rd[qq]);
            qa[h][s][3] = hh2pack(rc[qq + 8], rd[qq + 8]);
        }
    }

    float oacc[4][4][4];                   // [head][d-frag][pos]
#pragma unroll
    for (int i = 0; i < 4; i++)
#pragma unroll
        for (int j = 0; j < 4; j++)
#pragma unroll
            for (int q = 0; q < 4; q++) oacc[i][j][q] = 0.f;

    // smem ldsm bases (per-warp head block = wip*128 rows)
    const uint32_t kRow = smb + KS_OFF + ((wip * 128 + r16) * 40 + c8) * 2;
    const uint32_t vRow = smb + VS_OFF + ((wip * 128 + r2) * 40 + c2) * 2;
    char* pdA = smraw + PD_OFF + (p * 2 + wip) * 2176;        // own partials
    char* pdB = smraw + PD_OFF + (p * 2 + (wip ^ 1)) * 2176;  // partner's

    // prefetch one 32-wide k-tile (K + V) into buffer kt%3
    auto PREFETCH = [&](int kt2) {
        if (kt2 <= 31) {
            const int k0 = kt2 * 32;
            const int bo = (kt2 % 3) * 20480;
#pragma unroll
            for (int c = 0; c < 4; c++) {
                int idx = c * 256 + t;
                int row = idx >> 2;
                int col = (idx & 3) * 8;
                CP_ASYNC16(smb + KS_OFF + bo + row * 80 + col * 2,
                           qbh + (size_t)(256 + row) * HW + k0 + col);
                CP_ASYNC16(smb + VS_OFF + bo + row * 80 + col * 2,
                           qbh + (size_t)(512 + row) * HW + k0 + col);
            }
        }
        CP_COMMIT();
    };

    PREFETCH(0);

    for (int kt = 0; kt < 32; kt++) {
        PREFETCH(kt + 1);          // writes buf (kt+1)%3: never collides with
                                   // readers of kt (this iter) or kt-1 (pre-bar)
        CP_WAIT1();                // own group kt landed
        __syncthreads();           // all groups kt visible; kt-1 readers done

        const uint32_t bo = (uint32_t)(kt % 3) * 20480;

        // ---- S + exp + in-register partial denominators (own 4 heads) ----
        uint32_t eh[4][4][2];      // e as half2, [head][k-frag][row-half]
        float pd[16];
#pragma unroll
        for (int i = 0; i < 16; i++) pd[i] = 0.f;

#pragma unroll
        for (int h = 0; h < 4; h++) {
            float sacc[4][4];
#pragma unroll
            for (int nf = 0; nf < 4; nf++)
#pragma unroll
                for (int q = 0; q < 4; q++) sacc[nf][q] = 0.f;
#pragma unroll
            for (int np = 0; np < 2; np++)
#pragma unroll
                for (int s = 0; s < 2; s++) {
                    uint32_t bk[4];
                    ldsm_x4t(bk, kRow + bo + h * 2560 + s * 1280 + np * 32);
                    mma16816(sacc[np * 2 + 0], qa[h][s], bk + 0);
                    mma16816(sacc[np * 2 + 1], qa[h][s], bk + 2);
                }
#pragma unroll
            for (int nf = 0; nf < 4; nf++) {
                float e0, e1, e2, e3;
                exp2pairf(pk2(sacc[nf][0], sacc[nf][1]), e0, e1);
                exp2pairf(pk2(sacc[nf][2], sacc[nf][3]), e2, e3);
                pd[nf * 4 + 0] += e0;
                pd[nf * 4 + 1] += e1;
                pd[nf * 4 + 2] += e2;
                pd[nf * 4 + 3] += e3;
                eh[h][nf][0] = pack_h2(e0, e1);
                eh[h][nf][1] = pack_h2(e2, e3);
            }
        }

        // ---- pair exchange of partial denominators (only softmax sync) ----
#pragma unroll
        for (int nf = 0; nf < 4; nf++) {
            *(float2*)(pdA + ((g)     * 34 + nf * 8 + 2 * t4) * 4) =
                make_float2(pd[nf * 4 + 0], pd[nf * 4 + 1]);
            *(float2*)(pdA + ((g + 8) * 34 + nf * 8 + 2 * t4) * 4) =
                make_float2(pd[nf * 4 + 2], pd[nf * 4 + 3]);
        }
        GROUP_BAR64(1 + p);
        float rcp[16];
#pragma unroll
        for (int nf = 0; nf < 4; nf++) {
            float2 q0 = *(float2*)(pdB + ((g)     * 34 + nf * 8 + 2 * t4) * 4);
            float2 q1 = *(float2*)(pdB + ((g + 8) * 34 + nf * 8 + 2 * t4) * 4);
            rcp[nf * 4 + 0] = frcpa(pd[nf * 4 + 0] + q0.x);
            rcp[nf * 4 + 1] = frcpa(pd[nf * 4 + 1] + q0.y);
            rcp[nf * 4 + 2] = frcpa(pd[nf * 4 + 2] + q1.x);
            rcp[nf * 4 + 3] = frcpa(pd[nf * 4 + 3] + q1.y);
        }

        // ---- O += W V (W repacked in-register; V from smem as B-frags) ----
#pragma unroll
        for (int h = 0; h < 4; h++) {
#pragma unroll
            for (int ks = 0; ks < 2; ks++) {
                uint32_t wfrag[4];
                {
                    float2 f = h2f2(eh[h][2 * ks][0]);
                    wfrag[0] = pack_h2(f.x * rcp[8 * ks + 0], f.y * rcp[8 * ks + 1]);
                }
                {
                    float2 f = h2f2(eh[h][2 * ks][1]);
                    wfrag[1] = pack_h2(f.x * rcp[8 * ks + 2], f.y * rcp[8 * ks + 3]);
                }
                {
                    float2 f = h2f2(eh[h][2 * ks + 1][0]);
                    wfrag[2] = pack_h2(f.x * rcp[8 * ks + 4], f.y * rcp[8 * ks + 5]);
                }
                {
                    float2 f = h2f2(eh[h][2 * ks + 1][1]);
                    wfrag[3] = pack_h2(f.x * rcp[8 * ks + 6], f.y * rcp[8 * ks + 7]);
                }
#pragma unroll
                for (int db = 0; db < 2; db++) {
                    uint32_t vb[4];
                    ldsm_x4(vb, vRow + bo + h * 2560 + db * 1280 + ks * 32);
                    mma16816(oacc[h][db * 2 + 0], wfrag, vb + 0);
                    mma16816(oacc[h][db * 2 + 1], wfrag, vb + 2);
                }
            }
        }
    }

    // ---- epilogue: scrambled flat-reshape layout, fp16 ----
    // AF row = b*256 + gh*32 + (q>>5) = b*256 + gh*32 + qt*2 + (p>>1)
    // AF col = (q&31)*32 + d, with q&31 = (p&1)*16 + qrow
#pragma unroll
    for (int h = 0; h < 4; h++) {
        const int gh = wip * 4 + h;
        __half* ob = af + ((size_t)(b * 256 + gh * 32 + qt * 2 + (p >> 1))) * 1024
                     + (p & 1) * 512;
#pragma unroll
        for (int nd = 0; nd < 4; nd++) {
#pragma unroll
            for (int rh = 0; rh < 2; rh++) {
                int col = (g + 8 * rh) * 32 + nd * 8 + 2 * t4;
                *(uint32_t*)(ob + col) =
                    pack_h2(oacc[h][nd][rh * 2 + 0], oacc[h][nd][rh * 2 + 1]);
            }
        }
    }
}

// ---------------------------------------------------------------------------
extern "C" void kernel_launch(void* const* d_in, const int* in_sizes, int n_in,
                              void* d_out, int out_size)
{
    const float* x      = (const float*)d_in[0];   // [8,512,32,32]
    const float* w_qkv  = (const float*)d_in[1];   // [768,512]
    const float* b_qkv  = (const float*)d_in[2];   // [768]
    const float* w_attn = (const float*)d_in[3];   // [512,256]
    const float* b_attn = (const float*)d_in[4];   // [512]
    float* out = (float*)d_out;                    // [8,512,32,32]

    void* qkvp = nullptr;
    void* afp  = nullptr;
    cudaGetSymbolAddress(&qkvp, g_qkvh);
    cudaGetSymbolAddress(&afp,  g_afh);

    cudaFuncSetAttribute((const void*)gemm_mma<768, 512, 256, float, __half>,
                         cudaFuncAttributeMaxDynamicSharedMemorySize, GEMM_SMEM);
    cudaFuncSetAttribute((const void*)gemm_mma<512, 256, 0, __half, float>,
                         cudaFuncAttributeMaxDynamicSharedMemorySize, GEMM_SMEM);
    cudaFuncSetAttribute((const void*)attn_mma,
                         cudaFuncAttributeMaxDynamicSharedMemorySize, ATTN_SMEM);

    // 1) QKV projection (fp16 mma; bias; q rows scaled; fp16 output)
    gemm_mma<768, 512, 256, float, __half><<<dim3(8, 6, BATCH), 256, GEMM_SMEM>>>(
        w_qkv, x, b_qkv, (__half*)qkvp, 0.17677669529663687f);

    // 2) fp16 fused attention, in-register head softmax
    attn_mma<<<dim3(16, BATCH), 256, ATTN_SMEM>>>((const __half*)qkvp,
                                                  (__half*)afp);

    // 3) output projection (fp16 mma; fp16 input; fp32 output)
    gemm_mma<512, 256, 0, __half, float><<<dim3(8, 4, BATCH), 256, GEMM_SMEM>>>(
        w_attn, (const __half*)afp, b_attn, out, 1.0f);
}